// round 6
// baseline (speedup 1.0000x reference)
#include <cuda_runtime.h>
#include <cuda_bf16.h>
#include <math.h>
#include <stdint.h>

// ---------------------------------------------------------------------------
// Problem constants
// ---------------------------------------------------------------------------
#define S_   256
#define LA_  128
#define LB_  512
#define DQ_  256
#define DKV_ 265
#define DQK_ 512
#define DV_  512
#define KPAD 272
#define KP2  136     // KPAD/2 pairs
#define ROWS_A (S_ * LA_)   // 32768
#define ROWS_B (S_ * LB_)   // 131072

// Scratch (device globals). All bf16x2 arrays store pairs along the K axis.
__device__ float    g_Yq [(size_t)ROWS_A * DQK_];
__device__ float    g_Yk [(size_t)ROWS_B * DQK_];
__device__ float    g_Yv [(size_t)ROWS_B * DV_];
__device__ float    g_Yf [(size_t)ROWS_A * DQ_];
__device__ uint32_t g_Ah [(size_t)ROWS_A * 128], g_Al [(size_t)ROWS_A * 128];
__device__ uint32_t g_Bh [(size_t)ROWS_B * KP2], g_Bl [(size_t)ROWS_B * KP2];
__device__ uint32_t g_Wqh[512 * 128], g_Wql[512 * 128];
__device__ uint32_t g_Wkh[512 * KP2], g_Wkl[512 * KP2];
__device__ uint32_t g_Wvh[512 * KP2], g_Wvl[512 * KP2];
__device__ uint32_t g_Wfh[256 * 256], g_Wfl[256 * 256];
__device__ uint32_t g_qh [(size_t)ROWS_A * 256], g_ql [(size_t)ROWS_A * 256];
__device__ uint32_t g_kh [(size_t)ROWS_B * 256], g_kl [(size_t)ROWS_B * 256];
__device__ uint32_t g_vh [(size_t)ROWS_B * 256], g_vl [(size_t)ROWS_B * 256];
__device__ uint32_t g_wvh[(size_t)ROWS_A * 256], g_wvl[(size_t)ROWS_A * 256];
__device__ float    g_stats[8 * 512];
__device__ float    g_cnt[2];

// ---------------------------------------------------------------------------
// Helpers
// ---------------------------------------------------------------------------
__device__ __forceinline__ void split2(float x0, float x1, uint32_t& h, uint32_t& l) {
    uint32_t hp;
    asm("cvt.rn.bf16x2.f32 %0, %1, %2;" : "=r"(hp) : "f"(x1), "f"(x0));
    float h0 = __uint_as_float(hp << 16);
    float h1 = __uint_as_float(hp & 0xffff0000u);
    asm("cvt.rn.bf16x2.f32 %0, %1, %2;" : "=r"(l) : "f"(x1 - h1), "f"(x0 - h0));
    h = hp;
}
__device__ __forceinline__ float bf_lo(uint32_t u) { return __uint_as_float(u << 16); }
__device__ __forceinline__ float bf_hi(uint32_t u) { return __uint_as_float(u & 0xffff0000u); }

#define MMA_BF16(c, a, b)                                                  \
  asm volatile("mma.sync.aligned.m16n8k16.row.col.f32.bf16.bf16.f32 "      \
    "{%0,%1,%2,%3}, {%4,%5,%6,%7}, {%8,%9}, {%0,%1,%2,%3};"                \
    : "+f"(c[0]), "+f"(c[1]), "+f"(c[2]), "+f"(c[3])                       \
    : "r"(a[0]), "r"(a[1]), "r"(a[2]), "r"(a[3]), "r"(b[0]), "r"(b[1]))

#define CP_ASYNC16(smem_u32, gptr) \
  asm volatile("cp.async.cg.shared.global [%0], [%1], 16;" :: "r"(smem_u32), "l"(gptr))
#define CP_COMMIT() asm volatile("cp.async.commit_group;")
#define CP_WAIT1()  asm volatile("cp.async.wait_group 1;")
#define CP_WAIT0()  asm volatile("cp.async.wait_group 0;")

// ---------------------------------------------------------------------------
// Small init / convert kernels
// ---------------------------------------------------------------------------
__global__ void zero_stats_kernel() {
    int i = blockIdx.x * blockDim.x + threadIdx.x;
    if (i < 8 * 512) g_stats[i] = 0.0f;
}

__global__ void cnt_kernel(const int* __restrict__ a_lens,
                           const int* __restrict__ b_lens) {
    __shared__ int sh[256];
    int t = threadIdx.x;
    sh[t] = a_lens[t];
    __syncthreads();
    for (int o = 128; o; o >>= 1) { if (t < o) sh[t] += sh[t + o]; __syncthreads(); }
    if (t == 0) g_cnt[0] = (float)sh[0];
    __syncthreads();
    sh[t] = b_lens[t];
    __syncthreads();
    for (int o = 128; o; o >>= 1) { if (t < o) sh[t] += sh[t + o]; __syncthreads(); }
    if (t == 0) g_cnt[1] = (float)sh[0];
}

// Split rows of length Ksrc into bf16x2 hi/lo pair arrays of Kpairs (zero pad).
__global__ void convert_split(const float* __restrict__ src,
                              uint32_t* __restrict__ dh, uint32_t* __restrict__ dl,
                              int Ksrc, int Kpairs) {
    size_t r = blockIdx.x;
    for (int p = threadIdx.x; p < Kpairs; p += blockDim.x) {
        float x0 = (2 * p     < Ksrc) ? src[r * Ksrc + 2 * p]     : 0.0f;
        float x1 = (2 * p + 1 < Ksrc) ? src[r * Ksrc + 2 * p + 1] : 0.0f;
        uint32_t h, l;
        split2(x0, x1, h, l);
        dh[r * Kpairs + p] = h;
        dl[r * Kpairs + p] = l;
    }
}

// ---------------------------------------------------------------------------
// Tensor-core GEMM v5: pre-split bf16x2 operands, m16n8k16, cp.async double
// buffer, fused masked BN stats.  C = X W^T + bias  (X: M x 2Kp, W: N x 2Kp)
// 256 threads = 8 warps (2m x 4n), warp tile 64x32. Kp % 8 == 0.
// ---------------------------------------------------------------------------
#define TPR 12   // smem pair-row stride (words): conflict-free LDS.32 frags

__global__ __launch_bounds__(256)
void gemm_tc(const uint32_t* __restrict__ Xh, const uint32_t* __restrict__ Xl,
             const uint32_t* __restrict__ Wh, const uint32_t* __restrict__ Wl,
             const float* __restrict__ bias, float* __restrict__ C,
             int M, int N, int Kp,
             const int* __restrict__ lens, int Lshift,
             float* __restrict__ sumOut, float* __restrict__ sqOut) {
    __shared__ uint32_t sXh[2][128][TPR], sXl[2][128][TPR];
    __shared__ uint32_t sWh[2][128][TPR], sWl[2][128][TPR];

    int tid  = threadIdx.x;
    int warp = tid >> 5, lane = tid & 31;
    int wm = warp >> 2;          // 0..1
    int wn = warp & 3;           // 0..3
    int g  = lane >> 2, tig = lane & 3;
    size_t row0 = (size_t)blockIdx.y * 128;
    int    col0 = blockIdx.x * 128;

    float c[4][4][4];
#pragma unroll
    for (int mt = 0; mt < 4; mt++)
#pragma unroll
        for (int nt = 0; nt < 4; nt++)
#pragma unroll
            for (int i = 0; i < 4; i++) c[mt][nt][i] = 0.0f;

    int xr = tid >> 1;           // 0..127
    int xp = (tid & 1) * 4;      // pair offset 0 or 4

    const uint32_t* Xph = Xh + (row0 + xr) * (size_t)Kp + xp;
    const uint32_t* Xpl = Xl + (row0 + xr) * (size_t)Kp + xp;
    const uint32_t* Wph = Wh + (size_t)(col0 + xr) * Kp + xp;
    const uint32_t* Wpl = Wl + (size_t)(col0 + xr) * Kp + xp;

    uint32_t dxh[2] = { (uint32_t)__cvta_generic_to_shared(&sXh[0][xr][xp]),
                        (uint32_t)__cvta_generic_to_shared(&sXh[1][xr][xp]) };
    uint32_t dxl[2] = { (uint32_t)__cvta_generic_to_shared(&sXl[0][xr][xp]),
                        (uint32_t)__cvta_generic_to_shared(&sXl[1][xr][xp]) };
    uint32_t dwh[2] = { (uint32_t)__cvta_generic_to_shared(&sWh[0][xr][xp]),
                        (uint32_t)__cvta_generic_to_shared(&sWh[1][xr][xp]) };
    uint32_t dwl[2] = { (uint32_t)__cvta_generic_to_shared(&sWl[0][xr][xp]),
                        (uint32_t)__cvta_generic_to_shared(&sWl[1][xr][xp]) };

    int nk = Kp / 8;

    CP_ASYNC16(dxh[0], Xph);
    CP_ASYNC16(dxl[0], Xpl);
    CP_ASYNC16(dwh[0], Wph);
    CP_ASYNC16(dwl[0], Wpl);
    CP_COMMIT();

    for (int i = 0; i < nk; i++) {
        int buf = i & 1;
        if (i + 1 < nk) {
            int off = (i + 1) * 8;
            CP_ASYNC16(dxh[buf ^ 1], Xph + off);
            CP_ASYNC16(dxl[buf ^ 1], Xpl + off);
            CP_ASYNC16(dwh[buf ^ 1], Wph + off);
            CP_ASYNC16(dwl[buf ^ 1], Wpl + off);
            CP_COMMIT();
            CP_WAIT1();
        } else {
            CP_WAIT0();
        }
        __syncthreads();

        uint32_t ah[4][4], al[4][4];
#pragma unroll
        for (int mt = 0; mt < 4; mt++) {
            int r = wm * 64 + mt * 16 + g;
            ah[mt][0] = sXh[buf][r][tig];     al[mt][0] = sXl[buf][r][tig];
            ah[mt][1] = sXh[buf][r + 8][tig]; al[mt][1] = sXl[buf][r + 8][tig];
            ah[mt][2] = sXh[buf][r][tig + 4]; al[mt][2] = sXl[buf][r][tig + 4];
            ah[mt][3] = sXh[buf][r + 8][tig + 4]; al[mt][3] = sXl[buf][r + 8][tig + 4];
        }
#pragma unroll
        for (int nt = 0; nt < 4; nt++) {
            int n = wn * 32 + nt * 8 + g;
            uint32_t bh[2], bl[2];
            bh[0] = sWh[buf][n][tig];     bl[0] = sWl[buf][n][tig];
            bh[1] = sWh[buf][n][tig + 4]; bl[1] = sWl[buf][n][tig + 4];
#pragma unroll
            for (int mt = 0; mt < 4; mt++) {
                MMA_BF16(c[mt][nt], ah[mt], bh);   // hi*hi
                MMA_BF16(c[mt][nt], ah[mt], bl);   // hi*lo
                MMA_BF16(c[mt][nt], al[mt], bh);   // lo*hi
            }
        }
        __syncthreads();
    }

    // epilogue: bias, store, fused masked column stats
    int Lm1 = (1 << Lshift) - 1;
    float ssum[4][2], ssq[4][2];
#pragma unroll
    for (int nt = 0; nt < 4; nt++) {
        ssum[nt][0] = ssum[nt][1] = 0.0f;
        ssq[nt][0]  = ssq[nt][1]  = 0.0f;
    }

#pragma unroll
    for (int mt = 0; mt < 4; mt++) {
        size_t r0 = row0 + wm * 64 + mt * 16 + g;
        size_t r1 = r0 + 8;
        bool v0 = ((int)(r0 & Lm1)) < lens[r0 >> Lshift];
        bool v1 = ((int)(r1 & Lm1)) < lens[r1 >> Lshift];
#pragma unroll
        for (int nt = 0; nt < 4; nt++) {
            int cc = col0 + wn * 32 + nt * 8 + tig * 2;
            float b0 = bias[cc], b1 = bias[cc + 1];
            float y00 = c[mt][nt][0] + b0;
            float y01 = c[mt][nt][1] + b1;
            float y10 = c[mt][nt][2] + b0;
            float y11 = c[mt][nt][3] + b1;
            C[r0 * N + cc]     = y00;
            C[r0 * N + cc + 1] = y01;
            C[r1 * N + cc]     = y10;
            C[r1 * N + cc + 1] = y11;
            if (v0) {
                ssum[nt][0] += y00; ssq[nt][0] += y00 * y00;
                ssum[nt][1] += y01; ssq[nt][1] += y01 * y01;
            }
            if (v1) {
                ssum[nt][0] += y10; ssq[nt][0] += y10 * y10;
                ssum[nt][1] += y11; ssq[nt][1] += y11 * y11;
            }
        }
    }

#pragma unroll
    for (int o = 16; o >= 4; o >>= 1) {
#pragma unroll
        for (int nt = 0; nt < 4; nt++) {
#pragma unroll
            for (int j = 0; j < 2; j++) {
                ssum[nt][j] += __shfl_xor_sync(0xffffffffu, ssum[nt][j], o);
                ssq[nt][j]  += __shfl_xor_sync(0xffffffffu, ssq[nt][j],  o);
            }
        }
    }
    if (g == 0) {
#pragma unroll
        for (int nt = 0; nt < 4; nt++) {
            int cc = col0 + wn * 32 + nt * 8 + tig * 2;
#pragma unroll
            for (int j = 0; j < 2; j++) {
                atomicAdd(&sumOut[cc + j], ssum[nt][j]);
                atomicAdd(&sqOut[cc + j],  ssq[nt][j]);
            }
        }
    }
}

// ---------------------------------------------------------------------------
// BN apply + ReLU + L2 row-normalize.
//  split path (outH != 0): D == 512, writes bf16x2 hi/lo pair arrays.
//  fp32 path: D == 256, writes fp32 with row masking.
// ---------------------------------------------------------------------------
__global__ __launch_bounds__(128)
void bn_apply_kernel(const float* __restrict__ Y, int D,
                     const float* __restrict__ ssum, const float* __restrict__ ssq,
                     const float* __restrict__ cntp,
                     const float* __restrict__ gamma, const float* __restrict__ beta,
                     const int* __restrict__ lens, int L,
                     int normalize, int maskOut,
                     uint32_t* __restrict__ outH, uint32_t* __restrict__ outL,
                     float* __restrict__ outF) {
    int r = blockIdx.x;
    int sidx = r / L;
    bool valid = ((r - sidx * L) < lens[sidx]);
    float inv = 1.0f / (*cntp);
    int t = threadIdx.x;
    int active = D >> 2;               // threads carrying data (128 or 64)

    float z[4];
    float ss = 0.0f;
    if (t < active) {
        int cc = t * 4;
        float4 y = *reinterpret_cast<const float4*>(&Y[(size_t)r * D + cc]);
        float yv[4] = {y.x, y.y, y.z, y.w};
#pragma unroll
        for (int i = 0; i < 4; i++) {
            int ci = cc + i;
            float mean = ssum[ci] * inv;
            float var  = fmaxf(ssq[ci] * inv - mean * mean, 0.0f);
            float zz = (yv[i] - mean) * rsqrtf(var + 1e-5f) * gamma[ci] + beta[ci];
            zz = fmaxf(zz, 0.0f);
            z[i] = zz;
            ss += zz * zz;
        }
    } else {
        z[0] = z[1] = z[2] = z[3] = 0.0f;
    }

    __shared__ float red[4];
#pragma unroll
    for (int o = 16; o; o >>= 1) ss += __shfl_xor_sync(0xffffffffu, ss, o);
    if ((t & 31) == 0) red[t >> 5] = ss;
    __syncthreads();
    float tot = red[0] + red[1] + red[2] + red[3];

    float scale = 1.0f;
    if (normalize) scale = 1.0f / fmaxf(sqrtf(tot), 1e-12f);
    if (maskOut && !valid) scale = 0.0f;

    if (t < active) {
        float z0 = z[0] * scale, z1 = z[1] * scale;
        float z2 = z[2] * scale, z3 = z[3] * scale;
        if (outH) {
            uint32_t h0, l0, h1, l1;
            split2(z0, z1, h0, l0);
            split2(z2, z3, h1, l1);
            size_t base = (size_t)r * (D >> 1) + t * 2;
            *reinterpret_cast<uint2*>(&outH[base]) = make_uint2(h0, h1);
            *reinterpret_cast<uint2*>(&outL[base]) = make_uint2(l0, l1);
        } else {
            *reinterpret_cast<float4*>(&outF[(size_t)r * D + t * 4]) =
                make_float4(z0, z1, z2, z3);
        }
    }
}

// ---------------------------------------------------------------------------
// Tensor-core attention v2: pre-split q/k, split-free Phase A.
// One block per (s, 64 q rows). 512 threads, 16 warps = 2m x 8n, warp 32x64.
// ---------------------------------------------------------------------------
#define AST 520
#define KST 24
// smem words: sS 64*520 | sKh 512*12 | sKl 512*12 | sQh 64*12 | sQl 64*12
// phase B reuses (sKh..sKl) region as fp32 V [512][24]
#define ATT_SMEM_WORDS (64 * AST + 512 * TPR * 2 + 64 * TPR * 2)
#define ATT_SMEM_BYTES (ATT_SMEM_WORDS * 4)

__global__ __launch_bounds__(512)
void attention_tc(const uint32_t* __restrict__ qh, const uint32_t* __restrict__ ql,
                  const uint32_t* __restrict__ kh, const uint32_t* __restrict__ kl,
                  const uint32_t* __restrict__ vh, const uint32_t* __restrict__ vl,
                  const int* __restrict__ b_lens,
                  uint32_t* __restrict__ wvh, uint32_t* __restrict__ wvl) {
    extern __shared__ float sm[];
    float*    sS  = sm;                                   // [64][AST]
    uint32_t* sKh = (uint32_t*)(sm + 64 * AST);           // [512][TPR]
    uint32_t* sKl = sKh + 512 * TPR;
    uint32_t* sQh = sKl + 512 * TPR;                      // [64][TPR]
    uint32_t* sQl = sQh + 64 * TPR;
    float*    sV  = (float*)sKh;                          // phase B: [512][KST]

    int s   = blockIdx.x;
    int a0  = blockIdx.y * 64;
    int tid = threadIdx.x;
    int warp = tid >> 5, lane = tid & 31;
    int wm = warp >> 3;                // 0..1
    int wn = warp & 7;                 // 0..7
    int g  = lane >> 2, tig = lane & 3;
    int nb = b_lens[s];

    size_t qb = (size_t)(s * LA_ + a0) * 256;   // pair base
    size_t kb = (size_t)s * LB_ * 256;
    size_t vb = kb;

    float c[2][8][4];
#pragma unroll
    for (int mt = 0; mt < 2; mt++)
#pragma unroll
        for (int nt = 0; nt < 8; nt++)
#pragma unroll
            for (int i = 0; i < 4; i++) c[mt][nt][i] = 0.0f;

    // ---------------- Phase A: S = Q K^T (split-free) ----------------
    for (int p0 = 0; p0 < 256; p0 += 8) {
        {   // Q: 64 rows x 8 pairs
            int row = tid >> 3, p = tid & 7;
            sQh[row * TPR + p] = qh[qb + row * 256 + p0 + p];
            sQl[row * TPR + p] = ql[qb + row * 256 + p0 + p];
        }
        // K: 512 rows x 8 pairs (uint4 = 4 pairs)
#pragma unroll
        for (int i = 0; i < 2; i++) {
            int idx = tid + 512 * i;
            int row = idx >> 1, half = (idx & 1) * 4;
            *reinterpret_cast<uint4*>(&sKh[row * TPR + half]) =
                *reinterpret_cast<const uint4*>(&kh[kb + (size_t)row * 256 + p0 + half]);
            *reinterpret_cast<uint4*>(&sKl[row * TPR + half]) =
                *reinterpret_cast<const uint4*>(&kl[kb + (size_t)row * 256 + p0 + half]);
        }
        __syncthreads();

        uint32_t ah[2][4], al[2][4];
#pragma unroll
        for (int mt = 0; mt < 2; mt++) {
            int r = wm * 32 + mt * 16 + g;
            ah[mt][0] = sQh[r * TPR + tig];           al[mt][0] = sQl[r * TPR + tig];
            ah[mt][1] = sQh[(r + 8) * TPR + tig];     al[mt][1] = sQl[(r + 8) * TPR + tig];
            ah[mt][2] = sQh[r * TPR + tig + 4];       al[mt][2] = sQl[r * TPR + tig + 4];
            ah[mt][3] = sQh[(r + 8) * TPR + tig + 4]; al[mt][3] = sQl[(r + 8) * TPR + tig + 4];
        }
#pragma unroll
        for (int nt = 0; nt < 8; nt++) {
            int n = wn * 64 + nt * 8 + g;
            uint32_t bh[2], bl[2];
            bh[0] = sKh[n * TPR + tig];     bl[0] = sKl[n * TPR + tig];
            bh[1] = sKh[n * TPR + tig + 4]; bl[1] = sKl[n * TPR + tig + 4];
#pragma unroll
            for (int mt = 0; mt < 2; mt++) {
                MMA_BF16(c[mt][nt], ah[mt], bh);
                MMA_BF16(c[mt][nt], ah[mt], bl);
                MMA_BF16(c[mt][nt], al[mt], bh);
            }
        }
        __syncthreads();
    }

    const float scaler = 6.25f;
#pragma unroll
    for (int mt = 0; mt < 2; mt++) {
        int r = wm * 32 + mt * 16 + g;
#pragma unroll
        for (int nt = 0; nt < 8; nt++) {
            int col = wn * 64 + nt * 8 + tig * 2;
            float v0 = c[mt][nt][0] * scaler;
            float v1 = c[mt][nt][1] * scaler;
            float v2 = c[mt][nt][2] * scaler;
            float v3 = c[mt][nt][3] * scaler;
            sS[r * AST + col]           = (col     < nb) ? v0 : -1e30f;
            sS[r * AST + col + 1]       = (col + 1 < nb) ? v1 : -1e30f;
            sS[(r + 8) * AST + col]     = (col     < nb) ? v2 : -1e30f;
            sS[(r + 8) * AST + col + 1] = (col + 1 < nb) ? v3 : -1e30f;
        }
    }
    __syncthreads();

    // softmax: warp per 4 rows
#pragma unroll
    for (int rr = 0; rr < 4; rr++) {
        int row = warp * 4 + rr;
        float m = -1e30f;
        for (int cc = lane; cc < 512; cc += 32) m = fmaxf(m, sS[row * AST + cc]);
#pragma unroll
        for (int o = 16; o; o >>= 1) m = fmaxf(m, __shfl_xor_sync(0xffffffffu, m, o));
        float sum = 0.0f;
        for (int cc = lane; cc < 512; cc += 32) {
            float e = expf(sS[row * AST + cc] - m);
            sS[row * AST + cc] = e;
            sum += e;
        }
#pragma unroll
        for (int o = 16; o; o >>= 1) sum += __shfl_xor_sync(0xffffffffu, sum, o);
        float invs = 1.0f / sum;
        for (int cc = lane; cc < 512; cc += 32) sS[row * AST + cc] *= invs;
    }
    __syncthreads();

    // ---------------- Phase B: WV = P V ----------------
#pragma unroll
    for (int mt = 0; mt < 2; mt++)
#pragma unroll
        for (int nt = 0; nt < 8; nt++)
#pragma unroll
            for (int i = 0; i < 4; i++) c[mt][nt][i] = 0.0f;

    for (int b0 = 0; b0 < LB_; b0 += 16) {
        // stage V^T chunk [512 dv][16 b], reconstructing fp32 = hi + lo
#pragma unroll
        for (int i = 0; i < 4; i++) {
            int idx = tid + 512 * i;
            int kk = idx & 15, dg = idx >> 4;           // dg: dv group of 4
            size_t pb = vb + (size_t)(b0 + kk) * 256 + dg * 2;
            uint2 hp = *reinterpret_cast<const uint2*>(&vh[pb]);
            uint2 lp = *reinterpret_cast<const uint2*>(&vl[pb]);
            sV[(dg * 4 + 0) * KST + kk] = bf_lo(hp.x) + bf_lo(lp.x);
            sV[(dg * 4 + 1) * KST + kk] = bf_hi(hp.x) + bf_hi(lp.x);
            sV[(dg * 4 + 2) * KST + kk] = bf_lo(hp.y) + bf_lo(lp.y);
            sV[(dg * 4 + 3) * KST + kk] = bf_hi(hp.y) + bf_hi(lp.y);
        }
        __syncthreads();

        uint32_t ah[2][4], al[2][4];
#pragma unroll
        for (int mt = 0; mt < 2; mt++) {
            int r = wm * 32 + mt * 16 + g;
            float2 p0 = *reinterpret_cast<const float2*>(&sS[r * AST + b0 + 2 * tig]);
            float2 p1 = *reinterpret_cast<const float2*>(&sS[(r + 8) * AST + b0 + 2 * tig]);
            float2 p2 = *reinterpret_cast<const float2*>(&sS[r * AST + b0 + 2 * tig + 8]);
            float2 p3 = *reinterpret_cast<const float2*>(&sS[(r + 8) * AST + b0 + 2 * tig + 8]);
            split2(p0.x, p0.y, ah[mt][0], al[mt][0]);
            split2(p1.x, p1.y, ah[mt][1], al[mt][1]);
            split2(p2.x, p2.y, ah[mt][2], al[mt][2]);
            split2(p3.x, p3.y, ah[mt][3], al[mt][3]);
        }
#pragma unroll
        for (int nt = 0; nt < 8; nt++) {
            int n = wn * 64 + nt * 8 + g;
            float2 q0 = *reinterpret_cast<const float2*>(&sV[n * KST + 2 * tig]);
            float2 q1 = *reinterpret_cast<const float2*>(&sV[n * KST + 2 * tig + 8]);
            uint32_t bh[2], bl[2];
            split2(q0.x, q0.y, bh[0], bl[0]);
            split2(q1.x, q1.y, bh[1], bl[1]);
#pragma unroll
            for (int mt = 0; mt < 2; mt++) {
                MMA_BF16(c[mt][nt], ah[mt], bh);
                MMA_BF16(c[mt][nt], ah[mt], bl);
                MMA_BF16(c[mt][nt], al[mt], bh);
            }
        }
        __syncthreads();
    }

    // epilogue: write wv as split bf16x2 (pairs along dv)
    size_t wb = (size_t)(s * LA_ + a0) * 256;
#pragma unroll
    for (int mt = 0; mt < 2; mt++) {
        int r = wm * 32 + mt * 16 + g;
#pragma unroll
        for (int nt = 0; nt < 8; nt++) {
            int pidx = wn * 32 + nt * 4 + tig;
            uint32_t h0, l0, h1, l1;
            split2(c[mt][nt][0], c[mt][nt][1], h0, l0);
            split2(c[mt][nt][2], c[mt][nt][3], h1, l1);
            wvh[wb + (size_t)r * 256 + pidx]       = h0;
            wvl[wb + (size_t)r * 256 + pidx]       = l0;
            wvh[wb + (size_t)(r + 8) * 256 + pidx] = h1;
            wvl[wb + (size_t)(r + 8) * 256 + pidx] = l1;
        }
    }
}

// ---------------------------------------------------------------------------
// Launch
// ---------------------------------------------------------------------------
extern "C" void kernel_launch(void* const* d_in, const int* in_sizes, int n_in,
                              void* d_out, int out_size) {
    const float* A      = (const float*)d_in[0];
    const float* B      = (const float*)d_in[1];
    const int*   a_lens = (const int*)  d_in[2];
    const int*   b_lens = (const int*)  d_in[3];
    const float* Wq     = (const float*)d_in[4];
    const float* bq     = (const float*)d_in[5];
    const float* gq     = (const float*)d_in[6];
    const float* betaq  = (const float*)d_in[7];
    const float* Wk     = (const float*)d_in[8];
    const float* bk     = (const float*)d_in[9];
    const float* gk     = (const float*)d_in[10];
    const float* betak  = (const float*)d_in[11];
    const float* Wv     = (const float*)d_in[12];
    const float* bv     = (const float*)d_in[13];
    const float* gv     = (const float*)d_in[14];
    const float* betav  = (const float*)d_in[15];
    const float* Wf     = (const float*)d_in[16];
    const float* bf     = (const float*)d_in[17];
    const float* gf     = (const float*)d_in[18];
    const float* betaf  = (const float*)d_in[19];
    float* out = (float*)d_out;

    float *Yq, *Yk, *Yv, *Yf, *stats, *cnt;
    uint32_t *Ah, *Al, *Bh, *Bl, *Wqh, *Wql, *Wkh, *Wkl, *Wvh, *Wvl, *Wfh, *Wfl;
    uint32_t *qh, *ql, *kh, *kl, *vh, *vl, *wvh, *wvl;
    cudaGetSymbolAddress((void**)&Yq,  g_Yq);
    cudaGetSymbolAddress((void**)&Yk,  g_Yk);
    cudaGetSymbolAddress((void**)&Yv,  g_Yv);
    cudaGetSymbolAddress((void**)&Yf,  g_Yf);
    cudaGetSymbolAddress((void**)&Ah,  g_Ah);   cudaGetSymbolAddress((void**)&Al,  g_Al);
    cudaGetSymbolAddress((void**)&Bh,  g_Bh);   cudaGetSymbolAddress((void**)&Bl,  g_Bl);
    cudaGetSymbolAddress((void**)&Wqh, g_Wqh);  cudaGetSymbolAddress((void**)&Wql, g_Wql);
    cudaGetSymbolAddress((void**)&Wkh, g_Wkh);  cudaGetSymbolAddress((void**)&Wkl, g_Wkl);
    cudaGetSymbolAddress((void**)&Wvh, g_Wvh);  cudaGetSymbolAddress((void**)&Wvl, g_Wvl);
    cudaGetSymbolAddress((void**)&Wfh, g_Wfh);  cudaGetSymbolAddress((void**)&Wfl, g_Wfl);
    cudaGetSymbolAddress((void**)&qh,  g_qh);   cudaGetSymbolAddress((void**)&ql,  g_ql);
    cudaGetSymbolAddress((void**)&kh,  g_kh);   cudaGetSymbolAddress((void**)&kl,  g_kl);
    cudaGetSymbolAddress((void**)&vh,  g_vh);   cudaGetSymbolAddress((void**)&vl,  g_vl);
    cudaGetSymbolAddress((void**)&wvh, g_wvh);  cudaGetSymbolAddress((void**)&wvl, g_wvl);
    cudaGetSymbolAddress((void**)&stats, g_stats);
    cudaGetSymbolAddress((void**)&cnt, g_cnt);

    cudaFuncSetAttribute(attention_tc,
                         cudaFuncAttributeMaxDynamicSharedMemorySize, ATT_SMEM_BYTES);

    float* sum_q = stats + 0 * 512;
    float* sq_q  = stats + 1 * 512;
    float* sum_k = stats + 2 * 512;
    float* sq_k  = stats + 3 * 512;
    float* sum_v = stats + 4 * 512;
    float* sq_v  = stats + 5 * 512;
    float* sum_f = stats + 6 * 512;
    float* sq_f  = stats + 7 * 512;

    // 0) init + operand conversion (split to bf16x2 hi/lo pairs)
    zero_stats_kernel<<<16, 256>>>();
    cnt_kernel<<<1, 256>>>(a_lens, b_lens);
    convert_split<<<ROWS_A, 128>>>(A,  Ah,  Al,  DQ_,  128);
    convert_split<<<ROWS_B, 128>>>(B,  Bh,  Bl,  DKV_, KP2);
    convert_split<<<512, 128>>>(Wq, Wqh, Wql, DQ_,  128);
    convert_split<<<512, 128>>>(Wk, Wkh, Wkl, DKV_, KP2);
    convert_split<<<512, 128>>>(Wv, Wvh, Wvl, DKV_, KP2);
    convert_split<<<256, 128>>>(Wf, Wfh, Wfl, DV_,  256);

    // 1) projection GEMMs with fused masked stats
    gemm_tc<<<dim3(4, ROWS_A / 128), 256>>>(Ah, Al, Wqh, Wql, bq, Yq,
                                            ROWS_A, DQK_, 128, a_lens, 7, sum_q, sq_q);
    gemm_tc<<<dim3(4, ROWS_B / 128), 256>>>(Bh, Bl, Wkh, Wkl, bk, Yk,
                                            ROWS_B, DQK_, KP2, b_lens, 9, sum_k, sq_k);
    gemm_tc<<<dim3(4, ROWS_B / 128), 256>>>(Bh, Bl, Wvh, Wvl, bv, Yv,
                                            ROWS_B, DV_,  KP2, b_lens, 9, sum_v, sq_v);

    // 2) BN + ReLU + L2-normalize, emitting split bf16x2
    bn_apply_kernel<<<ROWS_A, 128>>>(Yq, DQK_, sum_q, sq_q, cnt + 0, gq, betaq,
                                     a_lens, LA_, 1, 0, qh, ql, nullptr);
    bn_apply_kernel<<<ROWS_B, 128>>>(Yk, DQK_, sum_k, sq_k, cnt + 1, gk, betak,
                                     b_lens, LB_, 1, 0, kh, kl, nullptr);
    bn_apply_kernel<<<ROWS_B, 128>>>(Yv, DV_,  sum_v, sq_v, cnt + 1, gv, betav,
                                     b_lens, LB_, 1, 0, vh, vl, nullptr);

    // 3) attention
    attention_tc<<<dim3(S_, LA_ / 64), 512, ATT_SMEM_BYTES>>>(
        qh, ql, kh, kl, vh, vl, b_lens, wvh, wvl);

    // 4) final projection (fused stats) + BN + ReLU + output mask
    gemm_tc<<<dim3(2, ROWS_A / 128), 256>>>(wvh, wvl, Wfh, Wfl, bf, Yf,
                                            ROWS_A, DQ_, 256, a_lens, 7, sum_f, sq_f);
    bn_apply_kernel<<<ROWS_A, 128>>>(Yf, DQ_, sum_f, sq_f, cnt + 0, gf, betaf,
                                     a_lens, LA_, 0, 1, nullptr, nullptr, out);
}

// round 8
// speedup vs baseline: 1.0185x; 1.0185x over previous
#include <cuda_runtime.h>
#include <cuda_bf16.h>
#include <math.h>
#include <stdint.h>

// ---------------------------------------------------------------------------
// Problem constants
// ---------------------------------------------------------------------------
#define S_   256
#define LA_  128
#define LB_  512
#define DQ_  256
#define DKV_ 265
#define DQK_ 512
#define DV_  512
#define KPAD 272            // DKV_ padded to multiple of 16

#define ROWS_A (S_ * LA_)   // 32768
#define ROWS_B (S_ * LB_)   // 131072

// Scratch (device globals; no allocation allowed)
__device__ __align__(16) float g_Yq [(size_t)ROWS_A * DQK_];
__device__ __align__(16) float g_Yk [(size_t)ROWS_B * DQK_];
__device__ __align__(16) float g_Yv [(size_t)ROWS_B * DV_];
__device__ __align__(16) float g_Ywv[(size_t)ROWS_A * DV_];
__device__ __align__(16) float g_Yf [(size_t)ROWS_A * DQ_];
__device__ __align__(16) float g_Bp [(size_t)ROWS_B * KPAD];
__device__ __align__(16) float g_Wkp[512 * KPAD];
__device__ __align__(16) float g_Wvp[512 * KPAD];
__device__ float g_stats[8 * 512];
__device__ float g_cnt[2];

// ---------------------------------------------------------------------------
// Helpers: bf16 2-term split + bf16 mma + cp.async
// ---------------------------------------------------------------------------
__device__ __forceinline__ void split2(float x0, float x1, uint32_t& h, uint32_t& l) {
    uint32_t hp;
    asm("cvt.rn.bf16x2.f32 %0, %1, %2;" : "=r"(hp) : "f"(x1), "f"(x0));
    float h0 = __uint_as_float(hp << 16);
    float h1 = __uint_as_float(hp & 0xffff0000u);
    asm("cvt.rn.bf16x2.f32 %0, %1, %2;" : "=r"(l) : "f"(x1 - h1), "f"(x0 - h0));
    h = hp;
}

#define MMA_BF16(c, a, b)                                                  \
  asm volatile("mma.sync.aligned.m16n8k16.row.col.f32.bf16.bf16.f32 "      \
    "{%0,%1,%2,%3}, {%4,%5,%6,%7}, {%8,%9}, {%0,%1,%2,%3};"                \
    : "+f"(c[0]), "+f"(c[1]), "+f"(c[2]), "+f"(c[3])                       \
    : "r"(a[0]), "r"(a[1]), "r"(a[2]), "r"(a[3]), "r"(b[0]), "r"(b[1]))

#define CP_ASYNC16(smem_u32a, gptr) \
  asm volatile("cp.async.cg.shared.global [%0], [%1], 16;" :: "r"(smem_u32a), "l"(gptr))
#define CP_COMMIT() asm volatile("cp.async.commit_group;")
#define CP_WAIT1()  asm volatile("cp.async.wait_group 1;")
#define CP_WAIT0()  asm volatile("cp.async.wait_group 0;")

// ---------------------------------------------------------------------------
// Small init kernels
// ---------------------------------------------------------------------------
__global__ void zero_stats_kernel() {
    int i = blockIdx.x * blockDim.x + threadIdx.x;
    if (i < 8 * 512) g_stats[i] = 0.0f;
}

__global__ void cnt_kernel(const int* __restrict__ a_lens,
                           const int* __restrict__ b_lens) {
    __shared__ int sh[256];
    int t = threadIdx.x;
    sh[t] = a_lens[t];
    __syncthreads();
    for (int o = 128; o; o >>= 1) { if (t < o) sh[t] += sh[t + o]; __syncthreads(); }
    if (t == 0) g_cnt[0] = (float)sh[0];
    __syncthreads();
    sh[t] = b_lens[t];
    __syncthreads();
    for (int o = 128; o; o >>= 1) { if (t < o) sh[t] += sh[t + o]; __syncthreads(); }
    if (t == 0) g_cnt[1] = (float)sh[0];
}

__global__ void pad_kernel(const float* __restrict__ src, float* __restrict__ dst,
                           int Ksrc) {
    size_t r = blockIdx.x;
    for (int k = threadIdx.x; k < KPAD; k += blockDim.x)
        dst[r * KPAD + k] = (k < Ksrc) ? src[r * Ksrc + k] : 0.0f;
}

// ---------------------------------------------------------------------------
// Tensor-core GEMM v6: bf16 2-term split, m16n8k16, cp.async double buffer,
// fused masked BN stats.  C = X W^T + bias.
// Block tile 128 x 256, 512 threads = 16 warps (2m x 8n), warp tile 64x32.
// K % 16 == 0.
// ---------------------------------------------------------------------------
#define TBK 16
#define TST 24   // smem row stride (words): conflict-free float2 frag loads

__global__ __launch_bounds__(512)
void gemm_tc(const float* __restrict__ X, const float* __restrict__ W,
             const float* __restrict__ bias, float* __restrict__ C,
             int M, int N, int K,
             const int* __restrict__ lens, int Lshift,
             float* __restrict__ sumOut, float* __restrict__ sqOut) {
    __shared__ float Xs[2][128][TST];
    __shared__ float Ws[2][256][TST];

    int tid  = threadIdx.x;
    int warp = tid >> 5, lane = tid & 31;
    int wm = warp >> 3;          // 0..1
    int wn = warp & 7;           // 0..7
    int g  = lane >> 2, tig = lane & 3;
    size_t row0 = (size_t)blockIdx.y * 128;
    int    col0 = blockIdx.x * 256;

    float c[4][4][4];
#pragma unroll
    for (int mt = 0; mt < 4; mt++)
#pragma unroll
        for (int nt = 0; nt < 4; nt++)
#pragma unroll
            for (int i = 0; i < 4; i++) c[mt][nt][i] = 0.0f;

    // staging assignments
    int xrow = tid >> 2;             // 0..127
    int xq   = (tid & 3) * 4;        // 0,4,8,12
    const float* Xp = X + (row0 + xrow) * (size_t)K + xq;
    uint32_t sxd[2] = { (uint32_t)__cvta_generic_to_shared(&Xs[0][xrow][xq]),
                        (uint32_t)__cvta_generic_to_shared(&Xs[1][xrow][xq]) };
    int wrow0 = tid >> 2;            // first W row handled
    int wrow1 = (tid + 512) >> 2;    // second
    int wq0 = (tid & 3) * 4, wq1 = ((tid + 512) & 3) * 4;  // same as wq0
    const float* Wp0 = W + (size_t)(col0 + wrow0) * K + wq0;
    const float* Wp1 = W + (size_t)(col0 + wrow1) * K + wq1;
    uint32_t swd0[2] = { (uint32_t)__cvta_generic_to_shared(&Ws[0][wrow0][wq0]),
                         (uint32_t)__cvta_generic_to_shared(&Ws[1][wrow0][wq0]) };
    uint32_t swd1[2] = { (uint32_t)__cvta_generic_to_shared(&Ws[0][wrow1][wq1]),
                         (uint32_t)__cvta_generic_to_shared(&Ws[1][wrow1][wq1]) };

    int nk = K / TBK;

    // prologue: stage tile 0 into buf 0
    CP_ASYNC16(sxd[0],  Xp);
    CP_ASYNC16(swd0[0], Wp0);
    CP_ASYNC16(swd1[0], Wp1);
    CP_COMMIT();

    for (int i = 0; i < nk; i++) {
        int buf = i & 1;
        if (i + 1 < nk) {
            int off = (i + 1) * TBK;
            CP_ASYNC16(sxd[buf ^ 1],  Xp + off);
            CP_ASYNC16(swd0[buf ^ 1], Wp0 + off);
            CP_ASYNC16(swd1[buf ^ 1], Wp1 + off);
            CP_COMMIT();
            CP_WAIT1();
        } else {
            CP_WAIT0();
        }
        __syncthreads();

        uint32_t ah[4][4], al[4][4];
#pragma unroll
        for (int mt = 0; mt < 4; mt++) {
            int r = wm * 64 + mt * 16 + g;
            float2 p0 = *reinterpret_cast<const float2*>(&Xs[buf][r][2 * tig]);
            float2 p1 = *reinterpret_cast<const float2*>(&Xs[buf][r + 8][2 * tig]);
            float2 p2 = *reinterpret_cast<const float2*>(&Xs[buf][r][2 * tig + 8]);
            float2 p3 = *reinterpret_cast<const float2*>(&Xs[buf][r + 8][2 * tig + 8]);
            split2(p0.x, p0.y, ah[mt][0], al[mt][0]);
            split2(p1.x, p1.y, ah[mt][1], al[mt][1]);
            split2(p2.x, p2.y, ah[mt][2], al[mt][2]);
            split2(p3.x, p3.y, ah[mt][3], al[mt][3]);
        }
#pragma unroll
        for (int nt = 0; nt < 4; nt++) {
            int n = wn * 32 + nt * 8 + g;
            float2 q0 = *reinterpret_cast<const float2*>(&Ws[buf][n][2 * tig]);
            float2 q1 = *reinterpret_cast<const float2*>(&Ws[buf][n][2 * tig + 8]);
            uint32_t bh[2], bl[2];
            split2(q0.x, q0.y, bh[0], bl[0]);
            split2(q1.x, q1.y, bh[1], bl[1]);
#pragma unroll
            for (int mt = 0; mt < 4; mt++) {
                MMA_BF16(c[mt][nt], ah[mt], bh);   // hi*hi
                MMA_BF16(c[mt][nt], ah[mt], bl);   // hi*lo
                MMA_BF16(c[mt][nt], al[mt], bh);   // lo*hi
            }
        }
        __syncthreads();
    }

    // epilogue: bias, store, fused masked column stats
    int Lm1 = (1 << Lshift) - 1;
    float ssum[4][2], ssq[4][2];
#pragma unroll
    for (int nt = 0; nt < 4; nt++) {
        ssum[nt][0] = ssum[nt][1] = 0.0f;
        ssq[nt][0]  = ssq[nt][1]  = 0.0f;
    }

#pragma unroll
    for (int mt = 0; mt < 4; mt++) {
        size_t r0 = row0 + wm * 64 + mt * 16 + g;
        size_t r1 = r0 + 8;
        bool v0 = ((int)(r0 & Lm1)) < lens[r0 >> Lshift];
        bool v1 = ((int)(r1 & Lm1)) < lens[r1 >> Lshift];
#pragma unroll
        for (int nt = 0; nt < 4; nt++) {
            int cc = col0 + wn * 32 + nt * 8 + tig * 2;
            float b0 = bias[cc], b1 = bias[cc + 1];
            float y00 = c[mt][nt][0] + b0;
            float y01 = c[mt][nt][1] + b1;
            float y10 = c[mt][nt][2] + b0;
            float y11 = c[mt][nt][3] + b1;
            C[r0 * N + cc]     = y00;
            C[r0 * N + cc + 1] = y01;
            C[r1 * N + cc]     = y10;
            C[r1 * N + cc + 1] = y11;
            if (v0) {
                ssum[nt][0] += y00; ssq[nt][0] += y00 * y00;
                ssum[nt][1] += y01; ssq[nt][1] += y01 * y01;
            }
            if (v1) {
                ssum[nt][0] += y10; ssq[nt][0] += y10 * y10;
                ssum[nt][1] += y11; ssq[nt][1] += y11 * y11;
            }
        }
    }

#pragma unroll
    for (int o = 16; o >= 4; o >>= 1) {
#pragma unroll
        for (int nt = 0; nt < 4; nt++) {
#pragma unroll
            for (int j = 0; j < 2; j++) {
                ssum[nt][j] += __shfl_xor_sync(0xffffffffu, ssum[nt][j], o);
                ssq[nt][j]  += __shfl_xor_sync(0xffffffffu, ssq[nt][j],  o);
            }
        }
    }
    if (g == 0) {
#pragma unroll
        for (int nt = 0; nt < 4; nt++) {
            int cc = col0 + wn * 32 + nt * 8 + tig * 2;
#pragma unroll
            for (int j = 0; j < 2; j++) {
                atomicAdd(&sumOut[cc + j], ssum[nt][j]);
                atomicAdd(&sqOut[cc + j],  ssq[nt][j]);
            }
        }
    }
}

// ---------------------------------------------------------------------------
// BN apply + ReLU + optional L2 row-normalize + optional row mask.
// 256 threads handle TWO rows per block (t<128: row 2b, t>=128: row 2b+1).
// ---------------------------------------------------------------------------
__global__ __launch_bounds__(256)
void bn_apply_kernel(float* __restrict__ Y, int D,
                     const float* __restrict__ ssum, const float* __restrict__ ssq,
                     const float* __restrict__ cntp,
                     const float* __restrict__ gamma, const float* __restrict__ beta,
                     const int* __restrict__ lens, int L,
                     int normalize, int maskOut, float* __restrict__ out) {
    int t  = threadIdx.x;
    int tl = t & 127;                       // lane within row-group
    int r  = blockIdx.x * 2 + (t >> 7);
    int sidx = r / L;
    bool valid = ((r - sidx * L) < lens[sidx]);
    float inv = 1.0f / (*cntp);
    int active = D >> 2;                    // 128 (D=512) or 64 (D=256)

    float z[4];
    float ss = 0.0f;
    if (tl < active) {
        int cc = tl * 4;
        float4 y = *reinterpret_cast<const float4*>(&Y[(size_t)r * D + cc]);
        float yv[4] = {y.x, y.y, y.z, y.w};
#pragma unroll
        for (int i = 0; i < 4; i++) {
            int ci = cc + i;
            float mean = ssum[ci] * inv;
            float var  = fmaxf(ssq[ci] * inv - mean * mean, 0.0f);
            float zz = (yv[i] - mean) * rsqrtf(var + 1e-5f) * gamma[ci] + beta[ci];
            zz = fmaxf(zz, 0.0f);
            z[i] = zz;
            ss += zz * zz;
        }
    } else {
        z[0] = z[1] = z[2] = z[3] = 0.0f;
    }

    __shared__ float red[8];
#pragma unroll
    for (int o = 16; o; o >>= 1) ss += __shfl_xor_sync(0xffffffffu, ss, o);
    if ((t & 31) == 0) red[t >> 5] = ss;
    __syncthreads();
    int rg = (t >> 7) * 4;
    float tot = red[rg] + red[rg + 1] + red[rg + 2] + red[rg + 3];

    float scale = 1.0f;
    if (normalize) scale = 1.0f / fmaxf(sqrtf(tot), 1e-12f);
    if (maskOut && !valid) scale = 0.0f;

    if (tl < active) {
        float* dst = out ? out : Y;
        *reinterpret_cast<float4*>(&dst[(size_t)r * D + tl * 4]) =
            make_float4(z[0] * scale, z[1] * scale, z[2] * scale, z[3] * scale);
    }
}

// ---------------------------------------------------------------------------
// Tensor-core attention (bf16 split, m16n8k16): one block per (s, 64 q rows).
// 512 threads, 16 warps = 2m x 8n, warp tile 32x64.  (identical to R5)
// ---------------------------------------------------------------------------
#define AST 520
#define KST 24
#define ATT_SMEM_FLOATS (64 * AST + 512 * KST + 64 * KST)
#define ATT_SMEM_BYTES  (ATT_SMEM_FLOATS * 4)

__global__ __launch_bounds__(512)
void attention_tc(const float* __restrict__ q, const float* __restrict__ k,
                  const float* __restrict__ v, const int* __restrict__ b_lens,
                  float* __restrict__ wv) {
    extern __shared__ float sm[];
    float* sS = sm;                    // [64][AST]
    float* sK = sm + 64 * AST;         // [512][KST]
    float* sQ = sK + 512 * KST;        // [64][KST]

    int s   = blockIdx.x;
    int a0  = blockIdx.y * 64;
    int tid = threadIdx.x;
    int warp = tid >> 5, lane = tid & 31;
    int wm = warp >> 3;
    int wn = warp & 7;
    int g  = lane >> 2, tig = lane & 3;
    int nb = b_lens[s];

    const float* qs = q + ((size_t)s * LA_ + a0) * DQK_;
    const float* ks = k + (size_t)s * LB_ * DQK_;
    const float* vs = v + (size_t)s * LB_ * DV_;

    float c[2][8][4];
#pragma unroll
    for (int mt = 0; mt < 2; mt++)
#pragma unroll
        for (int nt = 0; nt < 8; nt++)
#pragma unroll
            for (int i = 0; i < 4; i++) c[mt][nt][i] = 0.0f;

    for (int d0 = 0; d0 < DQK_; d0 += 16) {
        {
            int idx = tid * 2;
            int r = idx >> 4, cc = idx & 15;
            *reinterpret_cast<float2*>(&sQ[r * KST + cc]) =
                *reinterpret_cast<const float2*>(&qs[(size_t)r * DQK_ + d0 + cc]);
        }
#pragma unroll
        for (int i = 0; i < 4; i++) {
            int idx = tid + 512 * i;
            int b = idx >> 2, c4 = (idx & 3) * 4;
            *reinterpret_cast<float4*>(&sK[b * KST + c4]) =
                *reinterpret_cast<const float4*>(&ks[(size_t)b * DQK_ + d0 + c4]);
        }
        __syncthreads();

        uint32_t ah[2][4], al[2][4];
#pragma unroll
        for (int mt = 0; mt < 2; mt++) {
            int r = wm * 32 + mt * 16 + g;
            float2 p0 = *reinterpret_cast<const float2*>(&sQ[r * KST + 2 * tig]);
            float2 p1 = *reinterpret_cast<const float2*>(&sQ[(r + 8) * KST + 2 * tig]);
            float2 p2 = *reinterpret_cast<const float2*>(&sQ[r * KST + 2 * tig + 8]);
            float2 p3 = *reinterpret_cast<const float2*>(&sQ[(r + 8) * KST + 2 * tig + 8]);
            split2(p0.x, p0.y, ah[mt][0], al[mt][0]);
            split2(p1.x, p1.y, ah[mt][1], al[mt][1]);
            split2(p2.x, p2.y, ah[mt][2], al[mt][2]);
            split2(p3.x, p3.y, ah[mt][3], al[mt][3]);
        }
#pragma unroll
        for (int nt = 0; nt < 8; nt++) {
            int n = wn * 64 + nt * 8 + g;
            float2 q0 = *reinterpret_cast<const float2*>(&sK[n * KST + 2 * tig]);
            float2 q1 = *reinterpret_cast<const float2*>(&sK[n * KST + 2 * tig + 8]);
            uint32_t bh[2], bl[2];
            split2(q0.x, q0.y, bh[0], bl[0]);
            split2(q1.x, q1.y, bh[1], bl[1]);
#pragma unroll
            for (int mt = 0; mt < 2; mt++) {
                MMA_BF16(c[mt][nt], ah[mt], bh);
                MMA_BF16(c[mt][nt], ah[mt], bl);
                MMA_BF16(c[mt][nt], al[mt], bh);
            }
        }
        __syncthreads();
    }

    const float scaler = 6.25f;
#pragma unroll
    for (int mt = 0; mt < 2; mt++) {
        int r = wm * 32 + mt * 16 + g;
#pragma unroll
        for (int nt = 0; nt < 8; nt++) {
            int col = wn * 64 + nt * 8 + tig * 2;
            float v0 = c[mt][nt][0] * scaler;
            float v1 = c[mt][nt][1] * scaler;
            float v2 = c[mt][nt][2] * scaler;
            float v3 = c[mt][nt][3] * scaler;
            sS[r * AST + col]           = (col     < nb) ? v0 : -1e30f;
            sS[r * AST + col + 1]       = (col + 1 < nb) ? v1 : -1e30f;
            sS[(r + 8) * AST + col]     = (col     < nb) ? v2 : -1e30f;
            sS[(r + 8) * AST + col + 1] = (col + 1 < nb) ? v3 : -1e30f;
        }
    }
    __syncthreads();

#pragma unroll
    for (int rr = 0; rr < 4; rr++) {
        int row = warp * 4 + rr;
        float m = -1e30f;
        for (int cc = lane; cc < 512; cc += 32) m = fmaxf(m, sS[row * AST + cc]);
#pragma unroll
        for (int o = 16; o; o >>= 1) m = fmaxf(m, __shfl_xor_sync(0xffffffffu, m, o));
        float sum = 0.0f;
        for (int cc = lane; cc < 512; cc += 32) {
            float e = expf(sS[row * AST + cc] - m);
            sS[row * AST + cc] = e;
            sum += e;
        }
#pragma unroll
        for (int o = 16; o; o >>= 1) sum += __shfl_xor_sync(0xffffffffu, sum, o);
        float invs = 1.0f / sum;
        for (int cc = lane; cc < 512; cc += 32) sS[row * AST + cc] *= invs;
    }
    __syncthreads();

#pragma unroll
    for (int mt = 0; mt < 2; mt++)
#pragma unroll
        for (int nt = 0; nt < 8; nt++)
#pragma unroll
            for (int i = 0; i < 4; i++) c[mt][nt][i] = 0.0f;

    for (int b0 = 0; b0 < LB_; b0 += 16) {
#pragma unroll
        for (int i = 0; i < 4; i++) {
            int idx = tid + 512 * i;
            int kk = idx & 15, dg = idx >> 4;
            float4 vv = *reinterpret_cast<const float4*>(
                &vs[(size_t)(b0 + kk) * DV_ + dg * 4]);
            sK[(dg * 4 + 0) * KST + kk] = vv.x;
            sK[(dg * 4 + 1) * KST + kk] = vv.y;
            sK[(dg * 4 + 2) * KST + kk] = vv.z;
            sK[(dg * 4 + 3) * KST + kk] = vv.w;
        }
        __syncthreads();

        uint32_t ah[2][4], al[2][4];
#pragma unroll
        for (int mt = 0; mt < 2; mt++) {
            int r = wm * 32 + mt * 16 + g;
            float2 p0 = *reinterpret_cast<const float2*>(&sS[r * AST + b0 + 2 * tig]);
            float2 p1 = *reinterpret_cast<const float2*>(&sS[(r + 8) * AST + b0 + 2 * tig]);
            float2 p2 = *reinterpret_cast<const float2*>(&sS[r * AST + b0 + 2 * tig + 8]);
            float2 p3 = *reinterpret_cast<const float2*>(&sS[(r + 8) * AST + b0 + 2 * tig + 8]);
            split2(p0.x, p0.y, ah[mt][0], al[mt][0]);
            split2(p1.x, p1.y, ah[mt][1], al[mt][1]);
            split2(p2.x, p2.y, ah[mt][2], al[mt][2]);
            split2(p3.x, p3.y, ah[mt][3], al[mt][3]);
        }
#pragma unroll
        for (int nt = 0; nt < 8; nt++) {
            int n = wn * 64 + nt * 8 + g;
            float2 q0 = *reinterpret_cast<const float2*>(&sK[n * KST + 2 * tig]);
            float2 q1 = *reinterpret_cast<const float2*>(&sK[n * KST + 2 * tig + 8]);
            uint32_t bh[2], bl[2];
            split2(q0.x, q0.y, bh[0], bl[0]);
            split2(q1.x, q1.y, bh[1], bl[1]);
#pragma unroll
            for (int mt = 0; mt < 2; mt++) {
                MMA_BF16(c[mt][nt], ah[mt], bh);
                MMA_BF16(c[mt][nt], ah[mt], bl);
                MMA_BF16(c[mt][nt], al[mt], bh);
            }
        }
        __syncthreads();
    }

    float* wvp = wv + ((size_t)s * LA_ + a0) * DV_;
#pragma unroll
    for (int mt = 0; mt < 2; mt++) {
        int r = wm * 32 + mt * 16 + g;
#pragma unroll
        for (int nt = 0; nt < 8; nt++) {
            int col = wn * 64 + nt * 8 + tig * 2;
            wvp[(size_t)r * DV_ + col]           = c[mt][nt][0];
            wvp[(size_t)r * DV_ + col + 1]       = c[mt][nt][1];
            wvp[(size_t)(r + 8) * DV_ + col]     = c[mt][nt][2];
            wvp[(size_t)(r + 8) * DV_ + col + 1] = c[mt][nt][3];
        }
    }
}

// ---------------------------------------------------------------------------
// Launch
// ---------------------------------------------------------------------------
extern "C" void kernel_launch(void* const* d_in, const int* in_sizes, int n_in,
                              void* d_out, int out_size) {
    const float* A      = (const float*)d_in[0];
    const float* B      = (const float*)d_in[1];
    const int*   a_lens = (const int*)  d_in[2];
    const int*   b_lens = (const int*)  d_in[3];
    const float* Wq     = (const float*)d_in[4];
    const float* bq     = (const float*)d_in[5];
    const float* gq     = (const float*)d_in[6];
    const float* betaq  = (const float*)d_in[7];
    const float* Wk     = (const float*)d_in[8];
    const float* bk     = (const float*)d_in[9];
    const float* gk     = (const float*)d_in[10];
    const float* betak  = (const float*)d_in[11];
    const float* Wv     = (const float*)d_in[12];
    const float* bv     = (const float*)d_in[13];
    const float* gv     = (const float*)d_in[14];
    const float* betav  = (const float*)d_in[15];
    const float* Wf     = (const float*)d_in[16];
    const float* bf     = (const float*)d_in[17];
    const float* gf     = (const float*)d_in[18];
    const float* betaf  = (const float*)d_in[19];
    float* out = (float*)d_out;

    float *Yq, *Yk, *Yv, *Ywv, *Yf, *Bp, *Wkp, *Wvp, *stats, *cnt;
    cudaGetSymbolAddress((void**)&Yq,   g_Yq);
    cudaGetSymbolAddress((void**)&Yk,   g_Yk);
    cudaGetSymbolAddress((void**)&Yv,   g_Yv);
    cudaGetSymbolAddress((void**)&Ywv,  g_Ywv);
    cudaGetSymbolAddress((void**)&Yf,   g_Yf);
    cudaGetSymbolAddress((void**)&Bp,   g_Bp);
    cudaGetSymbolAddress((void**)&Wkp,  g_Wkp);
    cudaGetSymbolAddress((void**)&Wvp,  g_Wvp);
    cudaGetSymbolAddress((void**)&stats, g_stats);
    cudaGetSymbolAddress((void**)&cnt,  g_cnt);

    cudaFuncSetAttribute(attention_tc,
                         cudaFuncAttributeMaxDynamicSharedMemorySize, ATT_SMEM_BYTES);

    float* sum_q = stats + 0 * 512;
    float* sq_q  = stats + 1 * 512;
    float* sum_k = stats + 2 * 512;
    float* sq_k  = stats + 3 * 512;
    float* sum_v = stats + 4 * 512;
    float* sq_v  = stats + 5 * 512;
    float* sum_f = stats + 6 * 512;
    float* sq_f  = stats + 7 * 512;

    // 0) reset accumulators + pad odd-K operands
    zero_stats_kernel<<<16, 256>>>();
    cnt_kernel<<<1, 256>>>(a_lens, b_lens);
    pad_kernel<<<ROWS_B, 256>>>(B,  Bp,  DKV_);
    pad_kernel<<<512, 256>>>(Wk, Wkp, DKV_);
    pad_kernel<<<512, 256>>>(Wv, Wvp, DKV_);

    // 1) projection GEMMs with fused masked stats (128x256 tiles)
    gemm_tc<<<dim3(DQK_ / 256, ROWS_A / 128), 512>>>(A,  Wq,  bq, Yq, ROWS_A, DQK_, DQ_,
                                                     a_lens, 7, sum_q, sq_q);
    gemm_tc<<<dim3(DQK_ / 256, ROWS_B / 128), 512>>>(Bp, Wkp, bk, Yk, ROWS_B, DQK_, KPAD,
                                                     b_lens, 9, sum_k, sq_k);
    gemm_tc<<<dim3(DV_  / 256, ROWS_B / 128), 512>>>(Bp, Wvp, bv, Yv, ROWS_B, DV_,  KPAD,
                                                     b_lens, 9, sum_v, sq_v);

    // 2) BN + ReLU + L2-normalize (in-place), 2 rows per block
    bn_apply_kernel<<<ROWS_A / 2, 256>>>(Yq, DQK_, sum_q, sq_q, cnt + 0, gq, betaq,
                                         a_lens, LA_, 1, 0, nullptr);
    bn_apply_kernel<<<ROWS_B / 2, 256>>>(Yk, DQK_, sum_k, sq_k, cnt + 1, gk, betak,
                                         b_lens, LB_, 1, 0, nullptr);
    bn_apply_kernel<<<ROWS_B / 2, 256>>>(Yv, DV_,  sum_v, sq_v, cnt + 1, gv, betav,
                                         b_lens, LB_, 1, 0, nullptr);

    // 3) attention (tensor core)
    attention_tc<<<dim3(S_, LA_ / 64), 512, ATT_SMEM_BYTES>>>(Yq, Yk, Yv, b_lens, Ywv);

    // 4) final projection (fused stats) + BN + ReLU + output mask
    gemm_tc<<<dim3(DQ_ / 256, ROWS_A / 128), 512>>>(Ywv, Wf, bf, Yf, ROWS_A, DQ_, DV_,
                                                    a_lens, 7, sum_f, sq_f);
    bn_apply_kernel<<<ROWS_A / 2, 256>>>(Yf, DQ_, sum_f, sq_f, cnt + 0, gf, betaf,
                                         a_lens, LA_, 0, 1, out);
}

// round 10
// speedup vs baseline: 1.0927x; 1.0728x over previous
#include <cuda_runtime.h>
#include <cuda_bf16.h>
#include <math.h>
#include <stdint.h>

// ---------------------------------------------------------------------------
// Problem constants
// ---------------------------------------------------------------------------
#define S_   256
#define LA_  128
#define LB_  512
#define DQ_  256
#define DKV_ 265
#define DQK_ 512
#define DV_  512
#define KPAD 272            // DKV_ padded to multiple of 16 (16B-aligned rows)

#define ROWS_A (S_ * LA_)   // 32768
#define ROWS_B (S_ * LB_)   // 131072

// Scratch (device globals; no allocation allowed)
__device__ __align__(16) float g_Yq [(size_t)ROWS_A * DQK_];
__device__ __align__(16) float g_Yk [(size_t)ROWS_B * DQK_];
__device__ __align__(16) float g_Yv [(size_t)ROWS_B * DV_];
__device__ __align__(16) float g_Ywv[(size_t)ROWS_A * DV_];
__device__ __align__(16) float g_Yf [(size_t)ROWS_A * DQ_];
__device__ __align__(16) float g_Bp [(size_t)ROWS_B * KPAD];
__device__ __align__(16) float g_Wkp[512 * KPAD];
__device__ __align__(16) float g_Wvp[512 * KPAD];
__device__ float g_stats[8 * 512];
__device__ float g_cnt[2];

// ---------------------------------------------------------------------------
// Helpers
// ---------------------------------------------------------------------------
__device__ __forceinline__ void split2(float x0, float x1, uint32_t& h, uint32_t& l) {
    uint32_t hp;
    asm("cvt.rn.bf16x2.f32 %0, %1, %2;" : "=r"(hp) : "f"(x1), "f"(x0));
    float h0 = __uint_as_float(hp << 16);
    float h1 = __uint_as_float(hp & 0xffff0000u);
    asm("cvt.rn.bf16x2.f32 %0, %1, %2;" : "=r"(l) : "f"(x1 - h1), "f"(x0 - h0));
    h = hp;
}

#define MMA_BF16(c, a, b)                                                  \
  asm volatile("mma.sync.aligned.m16n8k16.row.col.f32.bf16.bf16.f32 "      \
    "{%0,%1,%2,%3}, {%4,%5,%6,%7}, {%8,%9}, {%0,%1,%2,%3};"                \
    : "+f"(c[0]), "+f"(c[1]), "+f"(c[2]), "+f"(c[3])                       \
    : "r"(a[0]), "r"(a[1]), "r"(a[2]), "r"(a[3]), "r"(b[0]), "r"(b[1]))

#define CP_ASYNC16(smem_a, gptr) \
  asm volatile("cp.async.cg.shared.global [%0], [%1], 16;" :: "r"(smem_a), "l"(gptr))
#define CP_COMMIT() asm volatile("cp.async.commit_group;")
#define CP_WAIT0()  asm volatile("cp.async.wait_group 0;" ::: "memory")

// ---------------------------------------------------------------------------
// Small init kernels
// ---------------------------------------------------------------------------
__global__ void zero_stats_kernel() {
    int i = blockIdx.x * blockDim.x + threadIdx.x;
    if (i < 8 * 512) g_stats[i] = 0.0f;
}

__global__ void cnt_kernel(const int* __restrict__ a_lens,
                           const int* __restrict__ b_lens) {
    __shared__ int sh[256];
    int t = threadIdx.x;
    sh[t] = a_lens[t];
    __syncthreads();
    for (int o = 128; o; o >>= 1) { if (t < o) sh[t] += sh[t + o]; __syncthreads(); }
    if (t == 0) g_cnt[0] = (float)sh[0];
    __syncthreads();
    sh[t] = b_lens[t];
    __syncthreads();
    for (int o = 128; o; o >>= 1) { if (t < o) sh[t] += sh[t + o]; __syncthreads(); }
    if (t == 0) g_cnt[1] = (float)sh[0];
}

// Pad rows of length Ksrc to KPAD (zero fill). One block per row.
__global__ void pad_kernel(const float* __restrict__ src, float* __restrict__ dst,
                           int Ksrc) {
    size_t r = blockIdx.x;
    for (int k = threadIdx.x; k < KPAD; k += blockDim.x)
        dst[r * KPAD + k] = (k < Ksrc) ? src[r * Ksrc + k] : 0.0f;
}

// ---------------------------------------------------------------------------
// Tensor-core GEMM: bf16 split, cp.async double buffer, ONE sync per k-iter,
// fused masked BN stats.  C = X W^T + bias.  K % 16 == 0, rows 16B-aligned.
// 256 threads = 8 warps (2m x 4n), warp tile 64x32, block tile 128x128.
// ---------------------------------------------------------------------------
#define TBK 16
#define TST 24

__global__ __launch_bounds__(256)
void gemm_tc(const float* __restrict__ X, const float* __restrict__ W,
             const float* __restrict__ bias, float* __restrict__ C,
             int M, int N, int K,
             const int* __restrict__ lens, int Lshift,
             float* __restrict__ sumOut, float* __restrict__ sqOut) {
    __shared__ float Xs[2][128][TST];
    __shared__ float Ws[2][128][TST];

    int tid  = threadIdx.x;
    int warp = tid >> 5, lane = tid & 31;
    int wm = warp >> 2;          // 0..1
    int wn = warp & 3;           // 0..3
    int g  = lane >> 2, tig = lane & 3;
    size_t row0 = (size_t)blockIdx.y * 128;
    int    col0 = blockIdx.x * 128;

    float c[4][4][4];
#pragma unroll
    for (int mt = 0; mt < 4; mt++)
#pragma unroll
        for (int nt = 0; nt < 4; nt++)
#pragma unroll
            for (int i = 0; i < 4; i++) c[mt][nt][i] = 0.0f;

    int xr = tid >> 1;           // 0..127
    int xk = (tid & 1) * 8;      // 0 or 8

    const float* Xp = X + (row0 + xr) * (size_t)K + xk;
    const float* Wp = W + (size_t)(col0 + xr) * K + xk;

    uint32_t sx[2] = { (uint32_t)__cvta_generic_to_shared(&Xs[0][xr][xk]),
                       (uint32_t)__cvta_generic_to_shared(&Xs[1][xr][xk]) };
    uint32_t sw[2] = { (uint32_t)__cvta_generic_to_shared(&Ws[0][xr][xk]),
                       (uint32_t)__cvta_generic_to_shared(&Ws[1][xr][xk]) };

    int nk = K / TBK;

    auto stage = [&](int i, int b) {
        int k0 = i * TBK;
        CP_ASYNC16(sx[b],      Xp + k0);
        CP_ASYNC16(sx[b] + 16, Xp + k0 + 4);
        CP_ASYNC16(sw[b],      Wp + k0);
        CP_ASYNC16(sw[b] + 16, Wp + k0 + 4);
        CP_COMMIT();
    };

    stage(0, 0);

    for (int i = 0; i < nk; i++) {
        int buf = i & 1;
        CP_WAIT0();
        __syncthreads();
        if (i + 1 < nk) stage(i + 1, buf ^ 1);

        uint32_t ah[4][4], al[4][4];
#pragma unroll
        for (int mt = 0; mt < 4; mt++) {
            int r = wm * 64 + mt * 16 + g;
            float2 p0 = *reinterpret_cast<const float2*>(&Xs[buf][r][2 * tig]);
            float2 p1 = *reinterpret_cast<const float2*>(&Xs[buf][r + 8][2 * tig]);
            float2 p2 = *reinterpret_cast<const float2*>(&Xs[buf][r][2 * tig + 8]);
            float2 p3 = *reinterpret_cast<const float2*>(&Xs[buf][r + 8][2 * tig + 8]);
            split2(p0.x, p0.y, ah[mt][0], al[mt][0]);
            split2(p1.x, p1.y, ah[mt][1], al[mt][1]);
            split2(p2.x, p2.y, ah[mt][2], al[mt][2]);
            split2(p3.x, p3.y, ah[mt][3], al[mt][3]);
        }
#pragma unroll
        for (int nt = 0; nt < 4; nt++) {
            int n = wn * 32 + nt * 8 + g;
            float2 q0 = *reinterpret_cast<const float2*>(&Ws[buf][n][2 * tig]);
            float2 q1 = *reinterpret_cast<const float2*>(&Ws[buf][n][2 * tig + 8]);
            uint32_t bh[2], bl[2];
            split2(q0.x, q0.y, bh[0], bl[0]);
            split2(q1.x, q1.y, bh[1], bl[1]);
#pragma unroll
            for (int mt = 0; mt < 4; mt++) {
                MMA_BF16(c[mt][nt], ah[mt], bh);   // hi*hi
                MMA_BF16(c[mt][nt], ah[mt], bl);   // hi*lo
                MMA_BF16(c[mt][nt], al[mt], bh);   // lo*hi
            }
        }
    }

    // epilogue: bias, store, fused masked column stats
    int Lm1 = (1 << Lshift) - 1;
    float ssum[4][2], ssq[4][2];
#pragma unroll
    for (int nt = 0; nt < 4; nt++) {
        ssum[nt][0] = ssum[nt][1] = 0.0f;
        ssq[nt][0]  = ssq[nt][1]  = 0.0f;
    }

#pragma unroll
    for (int mt = 0; mt < 4; mt++) {
        size_t r0 = row0 + wm * 64 + mt * 16 + g;
        size_t r1 = r0 + 8;
        bool v0 = ((int)(r0 & Lm1)) < lens[r0 >> Lshift];
        bool v1 = ((int)(r1 & Lm1)) < lens[r1 >> Lshift];
#pragma unroll
        for (int nt = 0; nt < 4; nt++) {
            int cc = col0 + wn * 32 + nt * 8 + tig * 2;
            float b0 = bias[cc], b1 = bias[cc + 1];
            float y00 = c[mt][nt][0] + b0;
            float y01 = c[mt][nt][1] + b1;
            float y10 = c[mt][nt][2] + b0;
            float y11 = c[mt][nt][3] + b1;
            C[r0 * N + cc]     = y00;
            C[r0 * N + cc + 1] = y01;
            C[r1 * N + cc]     = y10;
            C[r1 * N + cc + 1] = y11;
            if (v0) {
                ssum[nt][0] += y00; ssq[nt][0] += y00 * y00;
                ssum[nt][1] += y01; ssq[nt][1] += y01 * y01;
            }
            if (v1) {
                ssum[nt][0] += y10; ssq[nt][0] += y10 * y10;
                ssum[nt][1] += y11; ssq[nt][1] += y11 * y11;
            }
        }
    }

#pragma unroll
    for (int o = 16; o >= 4; o >>= 1) {
#pragma unroll
        for (int nt = 0; nt < 4; nt++) {
#pragma unroll
            for (int j = 0; j < 2; j++) {
                ssum[nt][j] += __shfl_xor_sync(0xffffffffu, ssum[nt][j], o);
                ssq[nt][j]  += __shfl_xor_sync(0xffffffffu, ssq[nt][j],  o);
            }
        }
    }
    if (g == 0) {
#pragma unroll
        for (int nt = 0; nt < 4; nt++) {
            int cc = col0 + wn * 32 + nt * 8 + tig * 2;
#pragma unroll
            for (int j = 0; j < 2; j++) {
                atomicAdd(&sumOut[cc + j], ssum[nt][j]);
                atomicAdd(&sqOut[cc + j],  ssq[nt][j]);
            }
        }
    }
}

// ---------------------------------------------------------------------------
// BN apply + ReLU + optional L2 row-normalize + optional row mask.
// 256 threads, two rows per block.
// ---------------------------------------------------------------------------
__global__ __launch_bounds__(256)
void bn_apply_kernel(float* __restrict__ Y, int D,
                     const float* __restrict__ ssum, const float* __restrict__ ssq,
                     const float* __restrict__ cntp,
                     const float* __restrict__ gamma, const float* __restrict__ beta,
                     const int* __restrict__ lens, int L,
                     int normalize, int maskOut, float* __restrict__ out) {
    int t  = threadIdx.x;
    int tl = t & 127;
    int r  = blockIdx.x * 2 + (t >> 7);
    int sidx = r / L;
    bool valid = ((r - sidx * L) < lens[sidx]);
    float inv = 1.0f / (*cntp);
    int active = D >> 2;

    float z[4];
    float ss = 0.0f;
    if (tl < active) {
        int cc = tl * 4;
        float4 y = *reinterpret_cast<const float4*>(&Y[(size_t)r * D + cc]);
        float yv[4] = {y.x, y.y, y.z, y.w};
#pragma unroll
        for (int i = 0; i < 4; i++) {
            int ci = cc + i;
            float mean = ssum[ci] * inv;
            float var  = fmaxf(ssq[ci] * inv - mean * mean, 0.0f);
            float zz = (yv[i] - mean) * rsqrtf(var + 1e-5f) * gamma[ci] + beta[ci];
            zz = fmaxf(zz, 0.0f);
            z[i] = zz;
            ss += zz * zz;
        }
    } else {
        z[0] = z[1] = z[2] = z[3] = 0.0f;
    }

    __shared__ float red[8];
#pragma unroll
    for (int o = 16; o; o >>= 1) ss += __shfl_xor_sync(0xffffffffu, ss, o);
    if ((t & 31) == 0) red[t >> 5] = ss;
    __syncthreads();
    int rg = (t >> 7) * 4;
    float tot = red[rg] + red[rg + 1] + red[rg + 2] + red[rg + 3];

    float scale = 1.0f;
    if (normalize) scale = 1.0f / fmaxf(sqrtf(tot), 1e-12f);
    if (maskOut && !valid) scale = 0.0f;

    if (tl < active) {
        float* dst = out ? out : Y;
        *reinterpret_cast<float4*>(&dst[(size_t)r * D + tl * 4]) =
            make_float4(z[0] * scale, z[1] * scale, z[2] * scale, z[3] * scale);
    }
}

// ---------------------------------------------------------------------------
// Tensor-core attention with double-buffered staging.
// One block per (s, 64 q rows). 512 threads, 16 warps = 2m x 8n, warp 32x64.
// smem: scores [64][520] | 2x K/V buf [512][20] | 2x Q buf [64][20]
// ---------------------------------------------------------------------------
#define AST 520
#define KBST 20
#define ATT_SMEM_FLOATS (64 * AST + 2 * 512 * KBST + 2 * 64 * KBST)
#define ATT_SMEM_BYTES  (ATT_SMEM_FLOATS * 4)   // 225280

__global__ __launch_bounds__(512)
void attention_tc(const float* __restrict__ q, const float* __restrict__ k,
                  const float* __restrict__ v, const int* __restrict__ b_lens,
                  float* __restrict__ wv) {
    extern __shared__ float sm[];
    float* sS  = sm;                          // [64][AST]
    float* sKb = sm + 64 * AST;               // 2 x [512][KBST]
    float* sQb = sKb + 2 * 512 * KBST;        // 2 x [64][KBST]

    int s   = blockIdx.x;
    int a0  = blockIdx.y * 64;
    int tid = threadIdx.x;
    int warp = tid >> 5, lane = tid & 31;
    int wm = warp >> 3;
    int wn = warp & 7;
    int g  = lane >> 2, tig = lane & 3;
    int nb = b_lens[s];

    const float* qs = q + ((size_t)s * LA_ + a0) * DQK_;
    const float* ks = k + (size_t)s * LB_ * DQK_;
    const float* vs = v + (size_t)s * LB_ * DV_;

    uint32_t sKa[2] = { (uint32_t)__cvta_generic_to_shared(sKb),
                        (uint32_t)__cvta_generic_to_shared(sKb + 512 * KBST) };
    uint32_t sQa[2] = { (uint32_t)__cvta_generic_to_shared(sQb),
                        (uint32_t)__cvta_generic_to_shared(sQb + 64 * KBST) };

    float c[2][8][4];
#pragma unroll
    for (int mt = 0; mt < 2; mt++)
#pragma unroll
        for (int nt = 0; nt < 8; nt++)
#pragma unroll
            for (int i = 0; i < 4; i++) c[mt][nt][i] = 0.0f;

    // ---------------- Phase A: S = Q K^T (cp.async double buffer) ----------
    auto stageA = [&](int ci, int b) {
        int d0 = ci * 16;
        if (tid < 256) {
            int r = tid >> 2, c4 = (tid & 3) * 4;
            CP_ASYNC16(sQa[b] + (r * KBST + c4) * 4,
                       qs + (size_t)r * DQK_ + d0 + c4);
        }
#pragma unroll
        for (int j = 0; j < 4; j++) {
            int idx = tid + 512 * j;
            int r = idx >> 2, c4 = (idx & 3) * 4;
            CP_ASYNC16(sKa[b] + (r * KBST + c4) * 4,
                       ks + (size_t)r * DQK_ + d0 + c4);
        }
        CP_COMMIT();
    };

    stageA(0, 0);

    for (int ci = 0; ci < 32; ci++) {
        int buf = ci & 1;
        CP_WAIT0();
        __syncthreads();
        if (ci + 1 < 32) stageA(ci + 1, buf ^ 1);

        const float* sQc = sQb + buf * 64 * KBST;
        const float* sKc = sKb + buf * 512 * KBST;

        uint32_t ah[2][4], al[2][4];
#pragma unroll
        for (int mt = 0; mt < 2; mt++) {
            int r = wm * 32 + mt * 16 + g;
            float2 p0 = *reinterpret_cast<const float2*>(&sQc[r * KBST + 2 * tig]);
            float2 p1 = *reinterpret_cast<const float2*>(&sQc[(r + 8) * KBST + 2 * tig]);
            float2 p2 = *reinterpret_cast<const float2*>(&sQc[r * KBST + 2 * tig + 8]);
            float2 p3 = *reinterpret_cast<const float2*>(&sQc[(r + 8) * KBST + 2 * tig + 8]);
            split2(p0.x, p0.y, ah[mt][0], al[mt][0]);
            split2(p1.x, p1.y, ah[mt][1], al[mt][1]);
            split2(p2.x, p2.y, ah[mt][2], al[mt][2]);
            split2(p3.x, p3.y, ah[mt][3], al[mt][3]);
        }
#pragma unroll
        for (int nt = 0; nt < 8; nt++) {
            int n = wn * 64 + nt * 8 + g;
            float2 q0 = *reinterpret_cast<const float2*>(&sKc[n * KBST + 2 * tig]);
            float2 q1 = *reinterpret_cast<const float2*>(&sKc[n * KBST + 2 * tig + 8]);
            uint32_t bh[2], bl[2];
            split2(q0.x, q0.y, bh[0], bl[0]);
            split2(q1.x, q1.y, bh[1], bl[1]);
#pragma unroll
            for (int mt = 0; mt < 2; mt++) {
                MMA_BF16(c[mt][nt], ah[mt], bh);
                MMA_BF16(c[mt][nt], ah[mt], bl);
                MMA_BF16(c[mt][nt], al[mt], bh);
            }
        }
    }

    // scale + mask -> sS
    const float scaler = 6.25f;
#pragma unroll
    for (int mt = 0; mt < 2; mt++) {
        int r = wm * 32 + mt * 16 + g;
#pragma unroll
        for (int nt = 0; nt < 8; nt++) {
            int col = wn * 64 + nt * 8 + tig * 2;
            float v0 = c[mt][nt][0] * scaler;
            float v1 = c[mt][nt][1] * scaler;
            float v2 = c[mt][nt][2] * scaler;
            float v3 = c[mt][nt][3] * scaler;
            sS[r * AST + col]           = (col     < nb) ? v0 : -1e30f;
            sS[r * AST + col + 1]       = (col + 1 < nb) ? v1 : -1e30f;
            sS[(r + 8) * AST + col]     = (col     < nb) ? v2 : -1e30f;
            sS[(r + 8) * AST + col + 1] = (col + 1 < nb) ? v3 : -1e30f;
        }
    }
    __syncthreads();

    // softmax: warp per 4 rows
#pragma unroll
    for (int rr = 0; rr < 4; rr++) {
        int row = warp * 4 + rr;
        float m = -1e30f;
        for (int cc = lane; cc < 512; cc += 32) m = fmaxf(m, sS[row * AST + cc]);
#pragma unroll
        for (int o = 16; o; o >>= 1) m = fmaxf(m, __shfl_xor_sync(0xffffffffu, m, o));
        float sum = 0.0f;
        for (int cc = lane; cc < 512; cc += 32) {
            float e = __expf(sS[row * AST + cc] - m);
            sS[row * AST + cc] = e;
            sum += e;
        }
#pragma unroll
        for (int o = 16; o; o >>= 1) sum += __shfl_xor_sync(0xffffffffu, sum, o);
        float invs = 1.0f / sum;
        for (int cc = lane; cc < 512; cc += 32) sS[row * AST + cc] *= invs;
    }
    __syncthreads();

    // ---------------- Phase B: WV = P V (double-buffered transpose) --------
#pragma unroll
    for (int mt = 0; mt < 2; mt++)
#pragma unroll
        for (int nt = 0; nt < 8; nt++)
#pragma unroll
            for (int i = 0; i < 4; i++) c[mt][nt][i] = 0.0f;

    auto stageB = [&](int bi, int b) {
        float* dst = sKb + b * 512 * KBST;
        int b0 = bi * 16;
#pragma unroll
        for (int j = 0; j < 4; j++) {
            int idx = tid + 512 * j;
            int kk = idx & 15, dg = idx >> 4;
            float4 vv = *reinterpret_cast<const float4*>(
                &vs[(size_t)(b0 + kk) * DV_ + dg * 4]);
            dst[(dg * 4 + 0) * KBST + kk] = vv.x;
            dst[(dg * 4 + 1) * KBST + kk] = vv.y;
            dst[(dg * 4 + 2) * KBST + kk] = vv.z;
            dst[(dg * 4 + 3) * KBST + kk] = vv.w;
        }
    };

    stageB(0, 0);
    __syncthreads();

    for (int bi = 0; bi < 32; bi++) {
        int buf = bi & 1;
        if (bi + 1 < 32) stageB(bi + 1, buf ^ 1);

        int b0 = bi * 16;
        const float* sVc = sKb + buf * 512 * KBST;

        uint32_t ah[2][4], al[2][4];
#pragma unroll
        for (int mt = 0; mt < 2; mt++) {
            int r = wm * 32 + mt * 16 + g;
            float2 p0 = *reinterpret_cast<const float2*>(&sS[r * AST + b0 + 2 * tig]);
            float2 p1 = *reinterpret_cast<const float2*>(&sS[(r + 8) * AST + b0 + 2 * tig]);
            float2 p2 = *reinterpret_cast<const float2*>(&sS[r * AST + b0 + 2 * tig + 8]);
            float2 p3 = *reinterpret_cast<const float2*>(&sS[(r + 8) * AST + b0 + 2 * tig + 8]);
            split2(p0.x, p0.y, ah[mt][0], al[mt][0]);
            split2(p1.x, p1.y, ah[mt][1], al[mt][1]);
            split2(p2.x, p2.y, ah[mt][2], al[mt][2]);
            split2(p3.x, p3.y, ah[mt][3], al[mt][3]);
        }
#pragma unroll
        for (int nt = 0; nt < 8; nt++) {
            int n = wn * 64 + nt * 8 + g;
            float2 q0 = *reinterpret_cast<const float2*>(&sVc[n * KBST + 2 * tig]);
            float2 q1 = *reinterpret_cast<const float2*>(&sVc[n * KBST + 2 * tig + 8]);
            uint32_t bh[2], bl[2];
            split2(q0.x, q0.y, bh[0], bl[0]);
            split2(q1.x, q1.y, bh[1], bl[1]);
#pragma unroll
            for (int mt = 0; mt < 2; mt++) {
                MMA_BF16(c[mt][nt], ah[mt], bh);
                MMA_BF16(c[mt][nt], ah[mt], bl);
                MMA_BF16(c[mt][nt], al[mt], bh);
            }
        }
        __syncthreads();
    }

    float* wvp = wv + ((size_t)s * LA_ + a0) * DV_;
#pragma unroll
    for (int mt = 0; mt < 2; mt++) {
        int r = wm * 32 + mt * 16 + g;
#pragma unroll
        for (int nt = 0; nt < 8; nt++) {
            int col = wn * 64 + nt * 8 + tig * 2;
            wvp[(size_t)r * DV_ + col]           = c[mt][nt][0];
            wvp[(size_t)r * DV_ + col + 1]       = c[mt][nt][1];
            wvp[(size_t)(r + 8) * DV_ + col]     = c[mt][nt][2];
            wvp[(size_t)(r + 8) * DV_ + col + 1] = c[mt][nt][3];
        }
    }
}

// ---------------------------------------------------------------------------
// Launch
// ---------------------------------------------------------------------------
extern "C" void kernel_launch(void* const* d_in, const int* in_sizes, int n_in,
                              void* d_out, int out_size) {
    const float* A      = (const float*)d_in[0];
    const float* B      = (const float*)d_in[1];
    const int*   a_lens = (const int*)  d_in[2];
    const int*   b_lens = (const int*)  d_in[3];
    const float* Wq     = (const float*)d_in[4];
    const float* bq     = (const float*)d_in[5];
    const float* gq     = (const float*)d_in[6];
    const float* betaq  = (const float*)d_in[7];
    const float* Wk     = (const float*)d_in[8];
    const float* bk     = (const float*)d_in[9];
    const float* gk     = (const float*)d_in[10];
    const float* betak  = (const float*)d_in[11];
    const float* Wv     = (const float*)d_in[12];
    const float* bv     = (const float*)d_in[13];
    const float* gv     = (const float*)d_in[14];
    const float* betav  = (const float*)d_in[15];
    const float* Wf     = (const float*)d_in[16];
    const float* bf     = (const float*)d_in[17];
    const float* gf     = (const float*)d_in[18];
    const float* betaf  = (const float*)d_in[19];
    float* out = (float*)d_out;

    float *Yq, *Yk, *Yv, *Ywv, *Yf, *Bp, *Wkp, *Wvp, *stats, *cnt;
    cudaGetSymbolAddress((void**)&Yq,   g_Yq);
    cudaGetSymbolAddress((void**)&Yk,   g_Yk);
    cudaGetSymbolAddress((void**)&Yv,   g_Yv);
    cudaGetSymbolAddress((void**)&Ywv,  g_Ywv);
    cudaGetSymbolAddress((void**)&Yf,   g_Yf);
    cudaGetSymbolAddress((void**)&Bp,   g_Bp);
    cudaGetSymbolAddress((void**)&Wkp,  g_Wkp);
    cudaGetSymbolAddress((void**)&Wvp,  g_Wvp);
    cudaGetSymbolAddress((void**)&stats, g_stats);
    cudaGetSymbolAddress((void**)&cnt,  g_cnt);

    cudaFuncSetAttribute(attention_tc,
                         cudaFuncAttributeMaxDynamicSharedMemorySize, ATT_SMEM_BYTES);

    float* sum_q = stats + 0 * 512;
    float* sq_q  = stats + 1 * 512;
    float* sum_k = stats + 2 * 512;
    float* sq_k  = stats + 3 * 512;
    float* sum_v = stats + 4 * 512;
    float* sq_v  = stats + 5 * 512;
    float* sum_f = stats + 6 * 512;
    float* sq_f  = stats + 7 * 512;

    // 0) init + pad odd-K operands (16B-aligned rows for cp.async)
    zero_stats_kernel<<<16, 256>>>();
    cnt_kernel<<<1, 256>>>(a_lens, b_lens);
    pad_kernel<<<ROWS_B, 256>>>(B,  Bp,  DKV_);
    pad_kernel<<<512, 256>>>(Wk, Wkp, DKV_);
    pad_kernel<<<512, 256>>>(Wv, Wvp, DKV_);

    // 1) projection GEMMs with fused masked stats
    gemm_tc<<<dim3(DQK_ / 128, ROWS_A / 128), 256>>>(A,  Wq,  bq, Yq,
        ROWS_A, DQK_, DQ_, a_lens, 7, sum_q, sq_q);
    gemm_tc<<<dim3(DQK_ / 128, ROWS_B / 128), 256>>>(Bp, Wkp, bk, Yk,
        ROWS_B, DQK_, KPAD, b_lens, 9, sum_k, sq_k);
    gemm_tc<<<dim3(DV_ / 128, ROWS_B / 128), 256>>>(Bp, Wvp, bv, Yv,
        ROWS_B, DV_, KPAD, b_lens, 9, sum_v, sq_v);

    // 2) BN + ReLU + L2-normalize (in-place)
    bn_apply_kernel<<<ROWS_A / 2, 256>>>(Yq, DQK_, sum_q, sq_q, cnt + 0, gq, betaq,
                                         a_lens, LA_, 1, 0, nullptr);
    bn_apply_kernel<<<ROWS_B / 2, 256>>>(Yk, DQK_, sum_k, sq_k, cnt + 1, gk, betak,
                                         b_lens, LB_, 1, 0, nullptr);
    bn_apply_kernel<<<ROWS_B / 2, 256>>>(Yv, DV_,  sum_v, sq_v, cnt + 1, gv, betav,
                                         b_lens, LB_, 1, 0, nullptr);

    // 3) attention
    attention_tc<<<dim3(S_, LA_ / 64), 512, ATT_SMEM_BYTES>>>(Yq, Yk, Yv, b_lens, Ywv);

    // 4) final projection + BN + ReLU + output mask
    gemm_tc<<<dim3(DQ_ / 128, ROWS_A / 128), 256>>>(Ywv, Wf, bf, Yf,
        ROWS_A, DQ_, DV_, a_lens, 7, sum_f, sq_f);
    bn_apply_kernel<<<ROWS_A / 2, 256>>>(Yf, DQ_, sum_f, sq_f, cnt + 0, gf, betaf,
                                         a_lens, LA_, 0, 1, out);
}

// round 11
// speedup vs baseline: 1.6536x; 1.5134x over previous
#include <cuda_runtime.h>
#include <cuda_bf16.h>
#include <math.h>
#include <stdint.h>

// ---------------------------------------------------------------------------
// Problem constants
// ---------------------------------------------------------------------------
#define S_   256
#define LA_  128
#define LB_  512
#define DQ_  256
#define DKV_ 265
#define DQK_ 512
#define DV_  512
#define KPAD 272            // DKV_ padded to multiple of 16 (16B-aligned rows)

#define ROWS_A (S_ * LA_)   // 32768
#define ROWS_B (S_ * LB_)   // 131072

// Scratch (device globals; no allocation allowed)
__device__ __align__(16) float g_Yq [(size_t)ROWS_A * DQK_];
__device__ __align__(16) float g_Yk [(size_t)ROWS_B * DQK_];
__device__ __align__(16) float g_Yv [(size_t)ROWS_B * DV_];
__device__ __align__(16) float g_Ywv[(size_t)ROWS_A * DV_];
__device__ __align__(16) float g_Yf [(size_t)ROWS_A * DQ_];
__device__ __align__(16) float g_Bp [(size_t)ROWS_B * KPAD];
__device__ __align__(16) float g_Wkp[512 * KPAD];
__device__ __align__(16) float g_Wvp[512 * KPAD];
__device__ float g_stats[8 * 512];
__device__ float g_cnt[2];

// ---------------------------------------------------------------------------
// Helpers
// ---------------------------------------------------------------------------
__device__ __forceinline__ void split2(float x0, float x1, uint32_t& h, uint32_t& l) {
    uint32_t hp;
    asm("cvt.rn.bf16x2.f32 %0, %1, %2;" : "=r"(hp) : "f"(x1), "f"(x0));
    float h0 = __uint_as_float(hp << 16);
    float h1 = __uint_as_float(hp & 0xffff0000u);
    asm("cvt.rn.bf16x2.f32 %0, %1, %2;" : "=r"(l) : "f"(x1 - h1), "f"(x0 - h0));
    h = hp;
}

#define MMA_BF16(c, a, b)                                                  \
  asm volatile("mma.sync.aligned.m16n8k16.row.col.f32.bf16.bf16.f32 "      \
    "{%0,%1,%2,%3}, {%4,%5,%6,%7}, {%8,%9}, {%0,%1,%2,%3};"                \
    : "+f"(c[0]), "+f"(c[1]), "+f"(c[2]), "+f"(c[3])                       \
    : "r"(a[0]), "r"(a[1]), "r"(a[2]), "r"(a[3]), "r"(b[0]), "r"(b[1]))

#define CP_ASYNC16(smem_a, gptr) \
  asm volatile("cp.async.cg.shared.global [%0], [%1], 16;" :: "r"(smem_a), "l"(gptr))
#define CP_COMMIT() asm volatile("cp.async.commit_group;")
#define CP_WAIT0()  asm volatile("cp.async.wait_group 0;" ::: "memory")

// ---------------------------------------------------------------------------
// Small init kernels
// ---------------------------------------------------------------------------
__global__ void zero_stats_kernel() {
    int i = blockIdx.x * blockDim.x + threadIdx.x;
    if (i < 8 * 512) g_stats[i] = 0.0f;
}

__global__ void cnt_kernel(const int* __restrict__ a_lens,
                           const int* __restrict__ b_lens) {
    __shared__ int sh[256];
    int t = threadIdx.x;
    sh[t] = a_lens[t];
    __syncthreads();
    for (int o = 128; o; o >>= 1) { if (t < o) sh[t] += sh[t + o]; __syncthreads(); }
    if (t == 0) g_cnt[0] = (float)sh[0];
    __syncthreads();
    sh[t] = b_lens[t];
    __syncthreads();
    for (int o = 128; o; o >>= 1) { if (t < o) sh[t] += sh[t + o]; __syncthreads(); }
    if (t == 0) g_cnt[1] = (float)sh[0];
}

// Pad rows of length Ksrc to KPAD (zero fill). One block per row.
__global__ void pad_kernel(const float* __restrict__ src, float* __restrict__ dst,
                           int Ksrc) {
    size_t r = blockIdx.x;
    for (int k = threadIdx.x; k < KPAD; k += blockDim.x)
        dst[r * KPAD + k] = (k < Ksrc) ? src[r * Ksrc + k] : 0.0f;
}

// ---------------------------------------------------------------------------
// Tensor-core GEMM: bf16 split, cp.async double buffer, one sync per k-iter,
// fused masked BN stats, FULLY-INVALID ROW-TILE SKIP.
// 256 threads = 8 warps (2m x 4n), warp tile 64x32, block tile 128x128.
// ---------------------------------------------------------------------------
#define TBK 16
#define TST 24

__global__ __launch_bounds__(256)
void gemm_tc(const float* __restrict__ X, const float* __restrict__ W,
             const float* __restrict__ bias, float* __restrict__ C,
             int M, int N, int K,
             const int* __restrict__ lens, int Lshift,
             float* __restrict__ sumOut, float* __restrict__ sqOut) {
    __shared__ float Xs[2][128][TST];
    __shared__ float Ws[2][128][TST];

    size_t row0 = (size_t)blockIdx.y * 128;
    int Lm1 = (1 << Lshift) - 1;
    // tile never crosses a sequence (128 | L). Skip if first row invalid.
    if (((int)(row0 & Lm1)) >= lens[row0 >> Lshift]) return;

    int tid  = threadIdx.x;
    int warp = tid >> 5, lane = tid & 31;
    int wm = warp >> 2;          // 0..1
    int wn = warp & 3;           // 0..3
    int g  = lane >> 2, tig = lane & 3;
    int    col0 = blockIdx.x * 128;

    float c[4][4][4];
#pragma unroll
    for (int mt = 0; mt < 4; mt++)
#pragma unroll
        for (int nt = 0; nt < 4; nt++)
#pragma unroll
            for (int i = 0; i < 4; i++) c[mt][nt][i] = 0.0f;

    int xr = tid >> 1;           // 0..127
    int xk = (tid & 1) * 8;      // 0 or 8

    const float* Xp = X + (row0 + xr) * (size_t)K + xk;
    const float* Wp = W + (size_t)(col0 + xr) * K + xk;

    uint32_t sx[2] = { (uint32_t)__cvta_generic_to_shared(&Xs[0][xr][xk]),
                       (uint32_t)__cvta_generic_to_shared(&Xs[1][xr][xk]) };
    uint32_t sw[2] = { (uint32_t)__cvta_generic_to_shared(&Ws[0][xr][xk]),
                       (uint32_t)__cvta_generic_to_shared(&Ws[1][xr][xk]) };

    int nk = K / TBK;

    auto stage = [&](int i, int b) {
        int k0 = i * TBK;
        CP_ASYNC16(sx[b],      Xp + k0);
        CP_ASYNC16(sx[b] + 16, Xp + k0 + 4);
        CP_ASYNC16(sw[b],      Wp + k0);
        CP_ASYNC16(sw[b] + 16, Wp + k0 + 4);
        CP_COMMIT();
    };

    stage(0, 0);

    for (int i = 0; i < nk; i++) {
        int buf = i & 1;
        CP_WAIT0();
        __syncthreads();
        if (i + 1 < nk) stage(i + 1, buf ^ 1);

        uint32_t ah[4][4], al[4][4];
#pragma unroll
        for (int mt = 0; mt < 4; mt++) {
            int r = wm * 64 + mt * 16 + g;
            float2 p0 = *reinterpret_cast<const float2*>(&Xs[buf][r][2 * tig]);
            float2 p1 = *reinterpret_cast<const float2*>(&Xs[buf][r + 8][2 * tig]);
            float2 p2 = *reinterpret_cast<const float2*>(&Xs[buf][r][2 * tig + 8]);
            float2 p3 = *reinterpret_cast<const float2*>(&Xs[buf][r + 8][2 * tig + 8]);
            split2(p0.x, p0.y, ah[mt][0], al[mt][0]);
            split2(p1.x, p1.y, ah[mt][1], al[mt][1]);
            split2(p2.x, p2.y, ah[mt][2], al[mt][2]);
            split2(p3.x, p3.y, ah[mt][3], al[mt][3]);
        }
#pragma unroll
        for (int nt = 0; nt < 4; nt++) {
            int n = wn * 32 + nt * 8 + g;
            float2 q0 = *reinterpret_cast<const float2*>(&Ws[buf][n][2 * tig]);
            float2 q1 = *reinterpret_cast<const float2*>(&Ws[buf][n][2 * tig + 8]);
            uint32_t bh[2], bl[2];
            split2(q0.x, q0.y, bh[0], bl[0]);
            split2(q1.x, q1.y, bh[1], bl[1]);
#pragma unroll
            for (int mt = 0; mt < 4; mt++) {
                MMA_BF16(c[mt][nt], ah[mt], bh);   // hi*hi
                MMA_BF16(c[mt][nt], ah[mt], bl);   // hi*lo
                MMA_BF16(c[mt][nt], al[mt], bh);   // lo*hi
            }
        }
    }

    // epilogue: bias, store, fused masked column stats
    float ssum[4][2], ssq[4][2];
#pragma unroll
    for (int nt = 0; nt < 4; nt++) {
        ssum[nt][0] = ssum[nt][1] = 0.0f;
        ssq[nt][0]  = ssq[nt][1]  = 0.0f;
    }

#pragma unroll
    for (int mt = 0; mt < 4; mt++) {
        size_t r0 = row0 + wm * 64 + mt * 16 + g;
        size_t r1 = r0 + 8;
        bool v0 = ((int)(r0 & Lm1)) < lens[r0 >> Lshift];
        bool v1 = ((int)(r1 & Lm1)) < lens[r1 >> Lshift];
#pragma unroll
        for (int nt = 0; nt < 4; nt++) {
            int cc = col0 + wn * 32 + nt * 8 + tig * 2;
            float b0 = bias[cc], b1 = bias[cc + 1];
            float y00 = c[mt][nt][0] + b0;
            float y01 = c[mt][nt][1] + b1;
            float y10 = c[mt][nt][2] + b0;
            float y11 = c[mt][nt][3] + b1;
            C[r0 * N + cc]     = y00;
            C[r0 * N + cc + 1] = y01;
            C[r1 * N + cc]     = y10;
            C[r1 * N + cc + 1] = y11;
            if (v0) {
                ssum[nt][0] += y00; ssq[nt][0] += y00 * y00;
                ssum[nt][1] += y01; ssq[nt][1] += y01 * y01;
            }
            if (v1) {
                ssum[nt][0] += y10; ssq[nt][0] += y10 * y10;
                ssum[nt][1] += y11; ssq[nt][1] += y11 * y11;
            }
        }
    }

#pragma unroll
    for (int o = 16; o >= 4; o >>= 1) {
#pragma unroll
        for (int nt = 0; nt < 4; nt++) {
#pragma unroll
            for (int j = 0; j < 2; j++) {
                ssum[nt][j] += __shfl_xor_sync(0xffffffffu, ssum[nt][j], o);
                ssq[nt][j]  += __shfl_xor_sync(0xffffffffu, ssq[nt][j],  o);
            }
        }
    }
    if (g == 0) {
#pragma unroll
        for (int nt = 0; nt < 4; nt++) {
            int cc = col0 + wn * 32 + nt * 8 + tig * 2;
#pragma unroll
            for (int j = 0; j < 2; j++) {
                atomicAdd(&sumOut[cc + j], ssum[nt][j]);
                atomicAdd(&sqOut[cc + j],  ssq[nt][j]);
            }
        }
    }
}

// ---------------------------------------------------------------------------
// BN apply + ReLU + optional L2 row-normalize + optional row mask.
// 256 threads, two rows per block. Invalid rows: skipped (or zeroed if
// maskOut) — their values are never observed downstream.
// ---------------------------------------------------------------------------
__global__ __launch_bounds__(256)
void bn_apply_kernel(float* __restrict__ Y, int D,
                     const float* __restrict__ ssum, const float* __restrict__ ssq,
                     const float* __restrict__ cntp,
                     const float* __restrict__ gamma, const float* __restrict__ beta,
                     const int* __restrict__ lens, int L,
                     int normalize, int maskOut, float* __restrict__ out) {
    int t  = threadIdx.x;
    int tl = t & 127;
    int r  = blockIdx.x * 2 + (t >> 7);
    int sidx = r / L;
    bool valid = ((r - sidx * L) < lens[sidx]);
    float inv = 1.0f / (*cntp);
    int active = D >> 2;

    float z[4] = {0.0f, 0.0f, 0.0f, 0.0f};
    float ss = 0.0f;
    if (tl < active && valid) {
        int cc = tl * 4;
        float4 y = *reinterpret_cast<const float4*>(&Y[(size_t)r * D + cc]);
        float yv[4] = {y.x, y.y, y.z, y.w};
#pragma unroll
        for (int i = 0; i < 4; i++) {
            int ci = cc + i;
            float mean = ssum[ci] * inv;
            float var  = fmaxf(ssq[ci] * inv - mean * mean, 0.0f);
            float zz = (yv[i] - mean) * rsqrtf(var + 1e-5f) * gamma[ci] + beta[ci];
            zz = fmaxf(zz, 0.0f);
            z[i] = zz;
            ss += zz * zz;
        }
    }

    __shared__ float red[8];
#pragma unroll
    for (int o = 16; o; o >>= 1) ss += __shfl_xor_sync(0xffffffffu, ss, o);
    if ((t & 31) == 0) red[t >> 5] = ss;
    __syncthreads();
    int rg = (t >> 7) * 4;
    float tot = red[rg] + red[rg + 1] + red[rg + 2] + red[rg + 3];

    float scale = 1.0f;
    if (normalize) scale = 1.0f / fmaxf(sqrtf(tot), 1e-12f);

    if (tl < active) {
        float* dst = out ? out : Y;
        if (valid) {
            *reinterpret_cast<float4*>(&dst[(size_t)r * D + tl * 4]) =
                make_float4(z[0] * scale, z[1] * scale, z[2] * scale, z[3] * scale);
        } else if (maskOut) {
            *reinterpret_cast<float4*>(&dst[(size_t)r * D + tl * 4]) =
                make_float4(0.0f, 0.0f, 0.0f, 0.0f);
        }
        // invalid && !maskOut: leave stale (bounded, masked downstream)
    }
}

// ---------------------------------------------------------------------------
// Tensor-core attention, double-buffered staging + valid-length bounding.
// One block per (s, 64 q rows). 512 threads, 16 warps = 2m x 8n, warp 32x64.
// ---------------------------------------------------------------------------
#define AST 520
#define KBST 20
#define ATT_SMEM_FLOATS (64 * AST + 2 * 512 * KBST + 2 * 64 * KBST)
#define ATT_SMEM_BYTES  (ATT_SMEM_FLOATS * 4)   // 225280

__global__ __launch_bounds__(512)
void attention_tc(const float* __restrict__ q, const float* __restrict__ k,
                  const float* __restrict__ v, const int* __restrict__ b_lens,
                  const int* __restrict__ a_lens, float* __restrict__ wv) {
    int s   = blockIdx.x;
    int a0  = blockIdx.y * 64;
    if (a0 >= a_lens[s]) return;    // whole q-tile invalid: wv rows stay 0

    extern __shared__ float sm[];
    float* sS  = sm;                          // [64][AST]
    float* sKb = sm + 64 * AST;               // 2 x [512][KBST]
    float* sQb = sKb + 2 * 512 * KBST;        // 2 x [64][KBST]

    int tid = threadIdx.x;
    int warp = tid >> 5, lane = tid & 31;
    int wm = warp >> 3;
    int wn = warp & 7;
    int g  = lane >> 2, tig = lane & 3;
    int nb = b_lens[s];
    int nb16 = (nb + 15) & ~15;     // staged/processed column extent
    int nbc  = nb16 >> 4;           // 16-col chunks in phase B

    const float* qs = q + ((size_t)s * LA_ + a0) * DQK_;
    const float* ks = k + (size_t)s * LB_ * DQK_;
    const float* vs = v + (size_t)s * LB_ * DV_;

    uint32_t sKa[2] = { (uint32_t)__cvta_generic_to_shared(sKb),
                        (uint32_t)__cvta_generic_to_shared(sKb + 512 * KBST) };
    uint32_t sQa[2] = { (uint32_t)__cvta_generic_to_shared(sQb),
                        (uint32_t)__cvta_generic_to_shared(sQb + 64 * KBST) };

    float c[2][8][4];
#pragma unroll
    for (int mt = 0; mt < 2; mt++)
#pragma unroll
        for (int nt = 0; nt < 8; nt++)
#pragma unroll
            for (int i = 0; i < 4; i++) c[mt][nt][i] = 0.0f;

    // ---------------- Phase A: S = Q K^T (d-chunks; b bounded by nb16) -----
    auto stageA = [&](int ci, int b) {
        int d0 = ci * 16;
        if (tid < 256) {
            int r = tid >> 2, c4 = (tid & 3) * 4;
            CP_ASYNC16(sQa[b] + (r * KBST + c4) * 4,
                       qs + (size_t)r * DQK_ + d0 + c4);
        }
#pragma unroll
        for (int j = 0; j < 4; j++) {
            int idx = tid + 512 * j;
            int r = idx >> 2, c4 = (idx & 3) * 4;
            if (r < nb16)
                CP_ASYNC16(sKa[b] + (r * KBST + c4) * 4,
                           ks + (size_t)r * DQK_ + d0 + c4);
        }
        CP_COMMIT();
    };

    stageA(0, 0);

    for (int ci = 0; ci < 32; ci++) {
        int buf = ci & 1;
        CP_WAIT0();
        __syncthreads();
        if (ci + 1 < 32) stageA(ci + 1, buf ^ 1);

        const float* sQc = sQb + buf * 64 * KBST;
        const float* sKc = sKb + buf * 512 * KBST;

        uint32_t ah[2][4], al[2][4];
#pragma unroll
        for (int mt = 0; mt < 2; mt++) {
            int r = wm * 32 + mt * 16 + g;
            float2 p0 = *reinterpret_cast<const float2*>(&sQc[r * KBST + 2 * tig]);
            float2 p1 = *reinterpret_cast<const float2*>(&sQc[(r + 8) * KBST + 2 * tig]);
            float2 p2 = *reinterpret_cast<const float2*>(&sQc[r * KBST + 2 * tig + 8]);
            float2 p3 = *reinterpret_cast<const float2*>(&sQc[(r + 8) * KBST + 2 * tig + 8]);
            split2(p0.x, p0.y, ah[mt][0], al[mt][0]);
            split2(p1.x, p1.y, ah[mt][1], al[mt][1]);
            split2(p2.x, p2.y, ah[mt][2], al[mt][2]);
            split2(p3.x, p3.y, ah[mt][3], al[mt][3]);
        }
#pragma unroll
        for (int nt = 0; nt < 8; nt++) {
            int nbase = wn * 64 + nt * 8;
            if (nbase >= nb) continue;          // dead b-columns: acc stays 0
            int n = nbase + g;
            float2 q0 = *reinterpret_cast<const float2*>(&sKc[n * KBST + 2 * tig]);
            float2 q1 = *reinterpret_cast<const float2*>(&sKc[n * KBST + 2 * tig + 8]);
            uint32_t bh[2], bl[2];
            split2(q0.x, q0.y, bh[0], bl[0]);
            split2(q1.x, q1.y, bh[1], bl[1]);
#pragma unroll
            for (int mt = 0; mt < 2; mt++) {
                MMA_BF16(c[mt][nt], ah[mt], bh);
                MMA_BF16(c[mt][nt], ah[mt], bl);
                MMA_BF16(c[mt][nt], al[mt], bh);
            }
        }
    }

    // scale + mask -> sS (all 512 cols; dead cols get -1e30)
    const float scaler = 6.25f;
#pragma unroll
    for (int mt = 0; mt < 2; mt++) {
        int r = wm * 32 + mt * 16 + g;
#pragma unroll
        for (int nt = 0; nt < 8; nt++) {
            int col = wn * 64 + nt * 8 + tig * 2;
            float v0 = c[mt][nt][0] * scaler;
            float v1 = c[mt][nt][1] * scaler;
            float v2 = c[mt][nt][2] * scaler;
            float v3 = c[mt][nt][3] * scaler;
            sS[r * AST + col]           = (col     < nb) ? v0 : -1e30f;
            sS[r * AST + col + 1]       = (col + 1 < nb) ? v1 : -1e30f;
            sS[(r + 8) * AST + col]     = (col     < nb) ? v2 : -1e30f;
            sS[(r + 8) * AST + col + 1] = (col + 1 < nb) ? v3 : -1e30f;
        }
    }
    __syncthreads();

    // softmax: warp per 4 rows, bounded to nb16 columns
#pragma unroll
    for (int rr = 0; rr < 4; rr++) {
        int row = warp * 4 + rr;
        float m = -1e30f;
        for (int cc = lane; cc < nb16; cc += 32) m = fmaxf(m, sS[row * AST + cc]);
#pragma unroll
        for (int o = 16; o; o >>= 1) m = fmaxf(m, __shfl_xor_sync(0xffffffffu, m, o));
        float sum = 0.0f;
        for (int cc = lane; cc < nb16; cc += 32) {
            float e = __expf(sS[row * AST + cc] - m);
            sS[row * AST + cc] = e;
            sum += e;
        }
#pragma unroll
        for (int o = 16; o; o >>= 1) sum += __shfl_xor_sync(0xffffffffu, sum, o);
        float invs = 1.0f / sum;
        for (int cc = lane; cc < nb16; cc += 32) sS[row * AST + cc] *= invs;
    }
    __syncthreads();

    // ---------------- Phase B: WV = P V (chunks bounded by nbc) ------------
#pragma unroll
    for (int mt = 0; mt < 2; mt++)
#pragma unroll
        for (int nt = 0; nt < 8; nt++)
#pragma unroll
            for (int i = 0; i < 4; i++) c[mt][nt][i] = 0.0f;

    auto stageB = [&](int bi, int b) {
        float* dst = sKb + b * 512 * KBST;
        int b0 = bi * 16;
#pragma unroll
        for (int j = 0; j < 4; j++) {
            int idx = tid + 512 * j;
            int kk = idx & 15, dg = idx >> 4;
            float4 vv = *reinterpret_cast<const float4*>(
                &vs[(size_t)(b0 + kk) * DV_ + dg * 4]);
            dst[(dg * 4 + 0) * KBST + kk] = vv.x;
            dst[(dg * 4 + 1) * KBST + kk] = vv.y;
            dst[(dg * 4 + 2) * KBST + kk] = vv.z;
            dst[(dg * 4 + 3) * KBST + kk] = vv.w;
        }
    };

    stageB(0, 0);
    __syncthreads();

    for (int bi = 0; bi < nbc; bi++) {
        int buf = bi & 1;
        if (bi + 1 < nbc) stageB(bi + 1, buf ^ 1);

        int b0 = bi * 16;
        const float* sVc = sKb + buf * 512 * KBST;

        uint32_t ah[2][4], al[2][4];
#pragma unroll
        for (int mt = 0; mt < 2; mt++) {
            int r = wm * 32 + mt * 16 + g;
            float2 p0 = *reinterpret_cast<const float2*>(&sS[r * AST + b0 + 2 * tig]);
            float2 p1 = *reinterpret_cast<const float2*>(&sS[(r + 8) * AST + b0 + 2 * tig]);
            float2 p2 = *reinterpret_cast<const float2*>(&sS[r * AST + b0 + 2 * tig + 8]);
            float2 p3 = *reinterpret_cast<const float2*>(&sS[(r + 8) * AST + b0 + 2 * tig + 8]);
            split2(p0.x, p0.y, ah[mt][0], al[mt][0]);
            split2(p1.x, p1.y, ah[mt][1], al[mt][1]);
            split2(p2.x, p2.y, ah[mt][2], al[mt][2]);
            split2(p3.x, p3.y, ah[mt][3], al[mt][3]);
        }
#pragma unroll
        for (int nt = 0; nt < 8; nt++) {
            int n = wn * 64 + nt * 8 + g;
            float2 q0 = *reinterpret_cast<const float2*>(&sVc[n * KBST + 2 * tig]);
            float2 q1 = *reinterpret_cast<const float2*>(&sVc[n * KBST + 2 * tig + 8]);
            uint32_t bh[2], bl[2];
            split2(q0.x, q0.y, bh[0], bl[0]);
            split2(q1.x, q1.y, bh[1], bl[1]);
#pragma unroll
            for (int mt = 0; mt < 2; mt++) {
                MMA_BF16(c[mt][nt], ah[mt], bh);
                MMA_BF16(c[mt][nt], ah[mt], bl);
                MMA_BF16(c[mt][nt], al[mt], bh);
            }
        }
        __syncthreads();
    }

    float* wvp = wv + ((size_t)s * LA_ + a0) * DV_;
#pragma unroll
    for (int mt = 0; mt < 2; mt++) {
        int r = wm * 32 + mt * 16 + g;
#pragma unroll
        for (int nt = 0; nt < 8; nt++) {
            int col = wn * 64 + nt * 8 + tig * 2;
            wvp[(size_t)r * DV_ + col]           = c[mt][nt][0];
            wvp[(size_t)r * DV_ + col + 1]       = c[mt][nt][1];
            wvp[(size_t)(r + 8) * DV_ + col]     = c[mt][nt][2];
            wvp[(size_t)(r + 8) * DV_ + col + 1] = c[mt][nt][3];
        }
    }
}

// ---------------------------------------------------------------------------
// Launch
// ---------------------------------------------------------------------------
extern "C" void kernel_launch(void* const* d_in, const int* in_sizes, int n_in,
                              void* d_out, int out_size) {
    const float* A      = (const float*)d_in[0];
    const float* B      = (const float*)d_in[1];
    const int*   a_lens = (const int*)  d_in[2];
    const int*   b_lens = (const int*)  d_in[3];
    const float* Wq     = (const float*)d_in[4];
    const float* bq     = (const float*)d_in[5];
    const float* gq     = (const float*)d_in[6];
    const float* betaq  = (const float*)d_in[7];
    const float* Wk     = (const float*)d_in[8];
    const float* bk     = (const float*)d_in[9];
    const float* gk     = (const float*)d_in[10];
    const float* betak  = (const float*)d_in[11];
    const float* Wv     = (const float*)d_in[12];
    const float* bv     = (const float*)d_in[13];
    const float* gv     = (const float*)d_in[14];
    const float* betav  = (const float*)d_in[15];
    const float* Wf     = (const float*)d_in[16];
    const float* bf     = (const float*)d_in[17];
    const float* gf     = (const float*)d_in[18];
    const float* betaf  = (const float*)d_in[19];
    float* out = (float*)d_out;

    float *Yq, *Yk, *Yv, *Ywv, *Yf, *Bp, *Wkp, *Wvp, *stats, *cnt;
    cudaGetSymbolAddress((void**)&Yq,   g_Yq);
    cudaGetSymbolAddress((void**)&Yk,   g_Yk);
    cudaGetSymbolAddress((void**)&Yv,   g_Yv);
    cudaGetSymbolAddress((void**)&Ywv,  g_Ywv);
    cudaGetSymbolAddress((void**)&Yf,   g_Yf);
    cudaGetSymbolAddress((void**)&Bp,   g_Bp);
    cudaGetSymbolAddress((void**)&Wkp,  g_Wkp);
    cudaGetSymbolAddress((void**)&Wvp,  g_Wvp);
    cudaGetSymbolAddress((void**)&stats, g_stats);
    cudaGetSymbolAddress((void**)&cnt,  g_cnt);

    cudaFuncSetAttribute(attention_tc,
                         cudaFuncAttributeMaxDynamicSharedMemorySize, ATT_SMEM_BYTES);

    float* sum_q = stats + 0 * 512;
    float* sq_q  = stats + 1 * 512;
    float* sum_k = stats + 2 * 512;
    float* sq_k  = stats + 3 * 512;
    float* sum_v = stats + 4 * 512;
    float* sq_v  = stats + 5 * 512;
    float* sum_f = stats + 6 * 512;
    float* sq_f  = stats + 7 * 512;

    // 0) init + pad odd-K operands (16B-aligned rows for cp.async)
    zero_stats_kernel<<<16, 256>>>();
    cnt_kernel<<<1, 256>>>(a_lens, b_lens);
    pad_kernel<<<ROWS_B, 256>>>(B,  Bp,  DKV_);
    pad_kernel<<<512, 256>>>(Wk, Wkp, DKV_);
    pad_kernel<<<512, 256>>>(Wv, Wvp, DKV_);

    // 1) projection GEMMs with fused masked stats + invalid-tile skip
    gemm_tc<<<dim3(DQK_ / 128, ROWS_A / 128), 256>>>(A,  Wq,  bq, Yq,
        ROWS_A, DQK_, DQ_, a_lens, 7, sum_q, sq_q);
    gemm_tc<<<dim3(DQK_ / 128, ROWS_B / 128), 256>>>(Bp, Wkp, bk, Yk,
        ROWS_B, DQK_, KPAD, b_lens, 9, sum_k, sq_k);
    gemm_tc<<<dim3(DV_ / 128, ROWS_B / 128), 256>>>(Bp, Wvp, bv, Yv,
        ROWS_B, DV_, KPAD, b_lens, 9, sum_v, sq_v);

    // 2) BN + ReLU + L2-normalize (in-place), invalid rows skipped
    bn_apply_kernel<<<ROWS_A / 2, 256>>>(Yq, DQK_, sum_q, sq_q, cnt + 0, gq, betaq,
                                         a_lens, LA_, 1, 0, nullptr);
    bn_apply_kernel<<<ROWS_B / 2, 256>>>(Yk, DQK_, sum_k, sq_k, cnt + 1, gk, betak,
                                         b_lens, LB_, 1, 0, nullptr);
    bn_apply_kernel<<<ROWS_B / 2, 256>>>(Yv, DV_,  sum_v, sq_v, cnt + 1, gv, betav,
                                         b_lens, LB_, 1, 0, nullptr);

    // 3) attention (valid-length bounded)
    attention_tc<<<dim3(S_, LA_ / 64), 512, ATT_SMEM_BYTES>>>(
        Yq, Yk, Yv, b_lens, a_lens, Ywv);

    // 4) final projection + BN + ReLU + output mask (explicit zeros)
    gemm_tc<<<dim3(DQ_ / 128, ROWS_A / 128), 256>>>(Ywv, Wf, bf, Yf,
        ROWS_A, DQ_, DV_, a_lens, 7, sum_f, sq_f);
    bn_apply_kernel<<<ROWS_A / 2, 256>>>(Yf, DQ_, sum_f, sq_f, cnt + 0, gf, betaf,
                                         a_lens, LA_, 0, 1, out);
}

// round 12
// speedup vs baseline: 1.7246x; 1.0429x over previous
#include <cuda_runtime.h>
#include <cuda_bf16.h>
#include <math.h>
#include <stdint.h>

// ---------------------------------------------------------------------------
// Problem constants
// ---------------------------------------------------------------------------
#define S_   256
#define LA_  128
#define LB_  512
#define DQ_  256
#define DKV_ 265
#define DQK_ 512
#define DV_  512
#define KPAD 272            // DKV_ padded to multiple of 16 (16B-aligned rows)

#define ROWS_A (S_ * LA_)   // 32768
#define ROWS_B (S_ * LB_)   // 131072

// Scratch (device globals; zero-initialized at load; no allocation allowed)
__device__ __align__(16) float g_Yq [(size_t)ROWS_A * DQK_];
__device__ __align__(16) float g_Yk [(size_t)ROWS_B * DQK_];
__device__ __align__(16) float g_Yv [(size_t)ROWS_B * DV_];
__device__ __align__(16) float g_Ywv[(size_t)ROWS_A * DV_];
__device__ __align__(16) float g_Yf [(size_t)ROWS_A * DQ_];
__device__ __align__(16) float g_Bp [(size_t)ROWS_B * KPAD];
__device__ __align__(16) float g_Wkp[512 * KPAD];
__device__ __align__(16) float g_Wvp[512 * KPAD];
__device__ float g_stats[8 * 512];
__device__ float g_cnt[2];

// ---------------------------------------------------------------------------
// Helpers
// ---------------------------------------------------------------------------
__device__ __forceinline__ void split2(float x0, float x1, uint32_t& h, uint32_t& l) {
    uint32_t hp;
    asm("cvt.rn.bf16x2.f32 %0, %1, %2;" : "=r"(hp) : "f"(x1), "f"(x0));
    float h0 = __uint_as_float(hp << 16);
    float h1 = __uint_as_float(hp & 0xffff0000u);
    asm("cvt.rn.bf16x2.f32 %0, %1, %2;" : "=r"(l) : "f"(x1 - h1), "f"(x0 - h0));
    h = hp;
}

#define MMA_BF16(c, a, b)                                                  \
  asm volatile("mma.sync.aligned.m16n8k16.row.col.f32.bf16.bf16.f32 "      \
    "{%0,%1,%2,%3}, {%4,%5,%6,%7}, {%8,%9}, {%0,%1,%2,%3};"                \
    : "+f"(c[0]), "+f"(c[1]), "+f"(c[2]), "+f"(c[3])                       \
    : "r"(a[0]), "r"(a[1]), "r"(a[2]), "r"(a[3]), "r"(b[0]), "r"(b[1]))

#define CP_ASYNC16(smem_a, gptr) \
  asm volatile("cp.async.cg.shared.global [%0], [%1], 16;" :: "r"(smem_a), "l"(gptr))
#define CP_COMMIT() asm volatile("cp.async.commit_group;")
#define CP_WAIT0()  asm volatile("cp.async.wait_group 0;" ::: "memory")

// ---------------------------------------------------------------------------
// Fused init: zero stats + length sums. One block, 256 threads.
// ---------------------------------------------------------------------------
__global__ void init_kernel(const int* __restrict__ a_lens,
                            const int* __restrict__ b_lens) {
    int t = threadIdx.x;
    for (int i = t; i < 8 * 512; i += 256) g_stats[i] = 0.0f;

    __shared__ int sh[256];
    sh[t] = a_lens[t];
    __syncthreads();
    for (int o = 128; o; o >>= 1) { if (t < o) sh[t] += sh[t + o]; __syncthreads(); }
    if (t == 0) g_cnt[0] = (float)sh[0];
    __syncthreads();
    sh[t] = b_lens[t];
    __syncthreads();
    for (int o = 128; o; o >>= 1) { if (t < o) sh[t] += sh[t + o]; __syncthreads(); }
    if (t == 0) g_cnt[1] = (float)sh[0];
}

// ---------------------------------------------------------------------------
// Fused pad: B (valid rows only), Wk, Wv -> KPAD-wide, zero tail.
// grid = ROWS_B + 1024 blocks.
// ---------------------------------------------------------------------------
__global__ void pad_all_kernel(const float* __restrict__ B,
                               const float* __restrict__ Wk,
                               const float* __restrict__ Wv,
                               const int* __restrict__ b_lens) {
    int bid = blockIdx.x;
    const float* src;
    float* dst;
    if (bid < ROWS_B) {
        int sidx = bid >> 9;
        if ((bid & 511) >= b_lens[sidx]) return;   // invalid row: Bp stays 0
        src = B + (size_t)bid * DKV_;
        dst = g_Bp + (size_t)bid * KPAD;
    } else if (bid < ROWS_B + 512) {
        int r = bid - ROWS_B;
        src = Wk + (size_t)r * DKV_;
        dst = g_Wkp + (size_t)r * KPAD;
    } else {
        int r = bid - ROWS_B - 512;
        src = Wv + (size_t)r * DKV_;
        dst = g_Wvp + (size_t)r * KPAD;
    }
    for (int k = threadIdx.x; k < KPAD; k += blockDim.x)
        dst[k] = (k < DKV_) ? src[k] : 0.0f;
}

// ---------------------------------------------------------------------------
// Tensor-core GEMM: bf16 split, cp.async double buffer, one sync per k-iter,
// fused masked BN stats, fully-invalid row-tile skip.
// 256 threads = 8 warps (2m x 4n), warp tile 64x32, block tile 128x128.
// ---------------------------------------------------------------------------
#define TBK 16
#define TST 24

__global__ __launch_bounds__(256)
void gemm_tc(const float* __restrict__ X, const float* __restrict__ W,
             const float* __restrict__ bias, float* __restrict__ C,
             int M, int N, int K,
             const int* __restrict__ lens, int Lshift,
             float* __restrict__ sumOut, float* __restrict__ sqOut) {
    __shared__ float Xs[2][128][TST];
    __shared__ float Ws[2][128][TST];

    size_t row0 = (size_t)blockIdx.y * 128;
    int Lm1 = (1 << Lshift) - 1;
    if (((int)(row0 & Lm1)) >= lens[row0 >> Lshift]) return;

    int tid  = threadIdx.x;
    int warp = tid >> 5, lane = tid & 31;
    int wm = warp >> 2;
    int wn = warp & 3;
    int g  = lane >> 2, tig = lane & 3;
    int    col0 = blockIdx.x * 128;

    float c[4][4][4];
#pragma unroll
    for (int mt = 0; mt < 4; mt++)
#pragma unroll
        for (int nt = 0; nt < 4; nt++)
#pragma unroll
            for (int i = 0; i < 4; i++) c[mt][nt][i] = 0.0f;

    int xr = tid >> 1;
    int xk = (tid & 1) * 8;

    const float* Xp = X + (row0 + xr) * (size_t)K + xk;
    const float* Wp = W + (size_t)(col0 + xr) * K + xk;

    uint32_t sx[2] = { (uint32_t)__cvta_generic_to_shared(&Xs[0][xr][xk]),
                       (uint32_t)__cvta_generic_to_shared(&Xs[1][xr][xk]) };
    uint32_t sw[2] = { (uint32_t)__cvta_generic_to_shared(&Ws[0][xr][xk]),
                       (uint32_t)__cvta_generic_to_shared(&Ws[1][xr][xk]) };

    int nk = K / TBK;

    auto stage = [&](int i, int b) {
        int k0 = i * TBK;
        CP_ASYNC16(sx[b],      Xp + k0);
        CP_ASYNC16(sx[b] + 16, Xp + k0 + 4);
        CP_ASYNC16(sw[b],      Wp + k0);
        CP_ASYNC16(sw[b] + 16, Wp + k0 + 4);
        CP_COMMIT();
    };

    stage(0, 0);

    for (int i = 0; i < nk; i++) {
        int buf = i & 1;
        CP_WAIT0();
        __syncthreads();
        if (i + 1 < nk) stage(i + 1, buf ^ 1);

        uint32_t ah[4][4], al[4][4];
#pragma unroll
        for (int mt = 0; mt < 4; mt++) {
            int r = wm * 64 + mt * 16 + g;
            float2 p0 = *reinterpret_cast<const float2*>(&Xs[buf][r][2 * tig]);
            float2 p1 = *reinterpret_cast<const float2*>(&Xs[buf][r + 8][2 * tig]);
            float2 p2 = *reinterpret_cast<const float2*>(&Xs[buf][r][2 * tig + 8]);
            float2 p3 = *reinterpret_cast<const float2*>(&Xs[buf][r + 8][2 * tig + 8]);
            split2(p0.x, p0.y, ah[mt][0], al[mt][0]);
            split2(p1.x, p1.y, ah[mt][1], al[mt][1]);
            split2(p2.x, p2.y, ah[mt][2], al[mt][2]);
            split2(p3.x, p3.y, ah[mt][3], al[mt][3]);
        }
#pragma unroll
        for (int nt = 0; nt < 4; nt++) {
            int n = wn * 32 + nt * 8 + g;
            float2 q0 = *reinterpret_cast<const float2*>(&Ws[buf][n][2 * tig]);
            float2 q1 = *reinterpret_cast<const float2*>(&Ws[buf][n][2 * tig + 8]);
            uint32_t bh[2], bl[2];
            split2(q0.x, q0.y, bh[0], bl[0]);
            split2(q1.x, q1.y, bh[1], bl[1]);
#pragma unroll
            for (int mt = 0; mt < 4; mt++) {
                MMA_BF16(c[mt][nt], ah[mt], bh);
                MMA_BF16(c[mt][nt], ah[mt], bl);
                MMA_BF16(c[mt][nt], al[mt], bh);
            }
        }
    }

    float ssum[4][2], ssq[4][2];
#pragma unroll
    for (int nt = 0; nt < 4; nt++) {
        ssum[nt][0] = ssum[nt][1] = 0.0f;
        ssq[nt][0]  = ssq[nt][1]  = 0.0f;
    }

#pragma unroll
    for (int mt = 0; mt < 4; mt++) {
        size_t r0 = row0 + wm * 64 + mt * 16 + g;
        size_t r1 = r0 + 8;
        bool v0 = ((int)(r0 & Lm1)) < lens[r0 >> Lshift];
        bool v1 = ((int)(r1 & Lm1)) < lens[r1 >> Lshift];
#pragma unroll
        for (int nt = 0; nt < 4; nt++) {
            int cc = col0 + wn * 32 + nt * 8 + tig * 2;
            float b0 = bias[cc], b1 = bias[cc + 1];
            float y00 = c[mt][nt][0] + b0;
            float y01 = c[mt][nt][1] + b1;
            float y10 = c[mt][nt][2] + b0;
            float y11 = c[mt][nt][3] + b1;
            C[r0 * N + cc]     = y00;
            C[r0 * N + cc + 1] = y01;
            C[r1 * N + cc]     = y10;
            C[r1 * N + cc + 1] = y11;
            if (v0) {
                ssum[nt][0] += y00; ssq[nt][0] += y00 * y00;
                ssum[nt][1] += y01; ssq[nt][1] += y01 * y01;
            }
            if (v1) {
                ssum[nt][0] += y10; ssq[nt][0] += y10 * y10;
                ssum[nt][1] += y11; ssq[nt][1] += y11 * y11;
            }
        }
    }

#pragma unroll
    for (int o = 16; o >= 4; o >>= 1) {
#pragma unroll
        for (int nt = 0; nt < 4; nt++) {
#pragma unroll
            for (int j = 0; j < 2; j++) {
                ssum[nt][j] += __shfl_xor_sync(0xffffffffu, ssum[nt][j], o);
                ssq[nt][j]  += __shfl_xor_sync(0xffffffffu, ssq[nt][j],  o);
            }
        }
    }
    if (g == 0) {
#pragma unroll
        for (int nt = 0; nt < 4; nt++) {
            int cc = col0 + wn * 32 + nt * 8 + tig * 2;
#pragma unroll
            for (int j = 0; j < 2; j++) {
                atomicAdd(&sumOut[cc + j], ssum[nt][j]);
                atomicAdd(&sqOut[cc + j],  ssq[nt][j]);
            }
        }
    }
}

// ---------------------------------------------------------------------------
// BN apply + ReLU + optional L2 row-normalize + optional row mask.
// 256 threads, two rows per block; invalid rows skipped / zeroed.
// ---------------------------------------------------------------------------
__global__ __launch_bounds__(256)
void bn_apply_kernel(float* __restrict__ Y, int D,
                     const float* __restrict__ ssum, const float* __restrict__ ssq,
                     const float* __restrict__ cntp,
                     const float* __restrict__ gamma, const float* __restrict__ beta,
                     const int* __restrict__ lens, int L,
                     int normalize, int maskOut, float* __restrict__ out) {
    int t  = threadIdx.x;
    int tl = t & 127;
    int r  = blockIdx.x * 2 + (t >> 7);
    int sidx = r / L;
    bool valid = ((r - sidx * L) < lens[sidx]);
    float inv = 1.0f / (*cntp);
    int active = D >> 2;

    float z[4] = {0.0f, 0.0f, 0.0f, 0.0f};
    float ss = 0.0f;
    if (tl < active && valid) {
        int cc = tl * 4;
        float4 y = *reinterpret_cast<const float4*>(&Y[(size_t)r * D + cc]);
        float yv[4] = {y.x, y.y, y.z, y.w};
#pragma unroll
        for (int i = 0; i < 4; i++) {
            int ci = cc + i;
            float mean = ssum[ci] * inv;
            float var  = fmaxf(ssq[ci] * inv - mean * mean, 0.0f);
            float zz = (yv[i] - mean) * rsqrtf(var + 1e-5f) * gamma[ci] + beta[ci];
            zz = fmaxf(zz, 0.0f);
            z[i] = zz;
            ss += zz * zz;
        }
    }

    __shared__ float red[8];
#pragma unroll
    for (int o = 16; o; o >>= 1) ss += __shfl_xor_sync(0xffffffffu, ss, o);
    if ((t & 31) == 0) red[t >> 5] = ss;
    __syncthreads();
    int rg = (t >> 7) * 4;
    float tot = red[rg] + red[rg + 1] + red[rg + 2] + red[rg + 3];

    float scale = 1.0f;
    if (normalize) scale = 1.0f / fmaxf(sqrtf(tot), 1e-12f);

    if (tl < active) {
        float* dst = out ? out : Y;
        if (valid) {
            *reinterpret_cast<float4*>(&dst[(size_t)r * D + tl * 4]) =
                make_float4(z[0] * scale, z[1] * scale, z[2] * scale, z[3] * scale);
        } else if (maskOut) {
            *reinterpret_cast<float4*>(&dst[(size_t)r * D + tl * 4]) =
                make_float4(0.0f, 0.0f, 0.0f, 0.0f);
        }
    }
}

// ---------------------------------------------------------------------------
// Tensor-core attention, double-buffered staging + valid-length bounding.
// One block per (s, 64 q rows). 512 threads, 16 warps = 2m x 8n, warp 32x64.
// ---------------------------------------------------------------------------
#define AST 520
#define KBST 20
#define ATT_SMEM_FLOATS (64 * AST + 2 * 512 * KBST + 2 * 64 * KBST)
#define ATT_SMEM_BYTES  (ATT_SMEM_FLOATS * 4)   // 225280

__global__ __launch_bounds__(512)
void attention_tc(const float* __restrict__ q, const float* __restrict__ k,
                  const float* __restrict__ v, const int* __restrict__ b_lens,
                  const int* __restrict__ a_lens, float* __restrict__ wv) {
    int s   = blockIdx.x;
    int a0  = blockIdx.y * 64;
    if (a0 >= a_lens[s]) return;    // whole q-tile invalid: wv rows stay 0

    extern __shared__ float sm[];
    float* sS  = sm;
    float* sKb = sm + 64 * AST;
    float* sQb = sKb + 2 * 512 * KBST;

    int tid = threadIdx.x;
    int warp = tid >> 5, lane = tid & 31;
    int wm = warp >> 3;
    int wn = warp & 7;
    int g  = lane >> 2, tig = lane & 3;
    int nb = b_lens[s];
    int nb16 = (nb + 15) & ~15;
    int nbc  = nb16 >> 4;

    const float* qs = q + ((size_t)s * LA_ + a0) * DQK_;
    const float* ks = k + (size_t)s * LB_ * DQK_;
    const float* vs = v + (size_t)s * LB_ * DV_;

    uint32_t sKa[2] = { (uint32_t)__cvta_generic_to_shared(sKb),
                        (uint32_t)__cvta_generic_to_shared(sKb + 512 * KBST) };
    uint32_t sQa[2] = { (uint32_t)__cvta_generic_to_shared(sQb),
                        (uint32_t)__cvta_generic_to_shared(sQb + 64 * KBST) };

    float c[2][8][4];
#pragma unroll
    for (int mt = 0; mt < 2; mt++)
#pragma unroll
        for (int nt = 0; nt < 8; nt++)
#pragma unroll
            for (int i = 0; i < 4; i++) c[mt][nt][i] = 0.0f;

    auto stageA = [&](int ci, int b) {
        int d0 = ci * 16;
        if (tid < 256) {
            int r = tid >> 2, c4 = (tid & 3) * 4;
            CP_ASYNC16(sQa[b] + (r * KBST + c4) * 4,
                       qs + (size_t)r * DQK_ + d0 + c4);
        }
#pragma unroll
        for (int j = 0; j < 4; j++) {
            int idx = tid + 512 * j;
            int r = idx >> 2, c4 = (idx & 3) * 4;
            if (r < nb16)
                CP_ASYNC16(sKa[b] + (r * KBST + c4) * 4,
                           ks + (size_t)r * DQK_ + d0 + c4);
        }
        CP_COMMIT();
    };

    stageA(0, 0);

    for (int ci = 0; ci < 32; ci++) {
        int buf = ci & 1;
        CP_WAIT0();
        __syncthreads();
        if (ci + 1 < 32) stageA(ci + 1, buf ^ 1);

        const float* sQc = sQb + buf * 64 * KBST;
        const float* sKc = sKb + buf * 512 * KBST;

        uint32_t ah[2][4], al[2][4];
#pragma unroll
        for (int mt = 0; mt < 2; mt++) {
            int r = wm * 32 + mt * 16 + g;
            float2 p0 = *reinterpret_cast<const float2*>(&sQc[r * KBST + 2 * tig]);
            float2 p1 = *reinterpret_cast<const float2*>(&sQc[(r + 8) * KBST + 2 * tig]);
            float2 p2 = *reinterpret_cast<const float2*>(&sQc[r * KBST + 2 * tig + 8]);
            float2 p3 = *reinterpret_cast<const float2*>(&sQc[(r + 8) * KBST + 2 * tig + 8]);
            split2(p0.x, p0.y, ah[mt][0], al[mt][0]);
            split2(p1.x, p1.y, ah[mt][1], al[mt][1]);
            split2(p2.x, p2.y, ah[mt][2], al[mt][2]);
            split2(p3.x, p3.y, ah[mt][3], al[mt][3]);
        }
#pragma unroll
        for (int nt = 0; nt < 8; nt++) {
            int nbase = wn * 64 + nt * 8;
            if (nbase >= nb) continue;
            int n = nbase + g;
            float2 q0 = *reinterpret_cast<const float2*>(&sKc[n * KBST + 2 * tig]);
            float2 q1 = *reinterpret_cast<const float2*>(&sKc[n * KBST + 2 * tig + 8]);
            uint32_t bh[2], bl[2];
            split2(q0.x, q0.y, bh[0], bl[0]);
            split2(q1.x, q1.y, bh[1], bl[1]);
#pragma unroll
            for (int mt = 0; mt < 2; mt++) {
                MMA_BF16(c[mt][nt], ah[mt], bh);
                MMA_BF16(c[mt][nt], ah[mt], bl);
                MMA_BF16(c[mt][nt], al[mt], bh);
            }
        }
    }

    const float scaler = 6.25f;
#pragma unroll
    for (int mt = 0; mt < 2; mt++) {
        int r = wm * 32 + mt * 16 + g;
#pragma unroll
        for (int nt = 0; nt < 8; nt++) {
            int col = wn * 64 + nt * 8 + tig * 2;
            float v0 = c[mt][nt][0] * scaler;
            float v1 = c[mt][nt][1] * scaler;
            float v2 = c[mt][nt][2] * scaler;
            float v3 = c[mt][nt][3] * scaler;
            sS[r * AST + col]           = (col     < nb) ? v0 : -1e30f;
            sS[r * AST + col + 1]       = (col + 1 < nb) ? v1 : -1e30f;
            sS[(r + 8) * AST + col]     = (col     < nb) ? v2 : -1e30f;
            sS[(r + 8) * AST + col + 1] = (col + 1 < nb) ? v3 : -1e30f;
        }
    }
    __syncthreads();

#pragma unroll
    for (int rr = 0; rr < 4; rr++) {
        int row = warp * 4 + rr;
        float m = -1e30f;
        for (int cc = lane; cc < nb16; cc += 32) m = fmaxf(m, sS[row * AST + cc]);
#pragma unroll
        for (int o = 16; o; o >>= 1) m = fmaxf(m, __shfl_xor_sync(0xffffffffu, m, o));
        float sum = 0.0f;
        for (int cc = lane; cc < nb16; cc += 32) {
            float e = __expf(sS[row * AST + cc] - m);
            sS[row * AST + cc] = e;
            sum += e;
        }
#pragma unroll
        for (int o = 16; o; o >>= 1) sum += __shfl_xor_sync(0xffffffffu, sum, o);
        float invs = 1.0f / sum;
        for (int cc = lane; cc < nb16; cc += 32) sS[row * AST + cc] *= invs;
    }
    __syncthreads();

#pragma unroll
    for (int mt = 0; mt < 2; mt++)
#pragma unroll
        for (int nt = 0; nt < 8; nt++)
#pragma unroll
            for (int i = 0; i < 4; i++) c[mt][nt][i] = 0.0f;

    auto stageB = [&](int bi, int b) {
        float* dst = sKb + b * 512 * KBST;
        int b0 = bi * 16;
#pragma unroll
        for (int j = 0; j < 4; j++) {
            int idx = tid + 512 * j;
            int kk = idx & 15, dg = idx >> 4;
            float4 vv = *reinterpret_cast<const float4*>(
                &vs[(size_t)(b0 + kk) * DV_ + dg * 4]);
            dst[(dg * 4 + 0) * KBST + kk] = vv.x;
            dst[(dg * 4 + 1) * KBST + kk] = vv.y;
            dst[(dg * 4 + 2) * KBST + kk] = vv.z;
            dst[(dg * 4 + 3) * KBST + kk] = vv.w;
        }
    };

    stageB(0, 0);
    __syncthreads();

    for (int bi = 0; bi < nbc; bi++) {
        int buf = bi & 1;
        if (bi + 1 < nbc) stageB(bi + 1, buf ^ 1);

        int b0 = bi * 16;
        const float* sVc = sKb + buf * 512 * KBST;

        uint32_t ah[2][4], al[2][4];
#pragma unroll
        for (int mt = 0; mt < 2; mt++) {
            int r = wm * 32 + mt * 16 + g;
            float2 p0 = *reinterpret_cast<const float2*>(&sS[r * AST + b0 + 2 * tig]);
            float2 p1 = *reinterpret_cast<const float2*>(&sS[(r + 8) * AST + b0 + 2 * tig]);
            float2 p2 = *reinterpret_cast<const float2*>(&sS[r * AST + b0 + 2 * tig + 8]);
            float2 p3 = *reinterpret_cast<const float2*>(&sS[(r + 8) * AST + b0 + 2 * tig + 8]);
            split2(p0.x, p0.y, ah[mt][0], al[mt][0]);
            split2(p1.x, p1.y, ah[mt][1], al[mt][1]);
            split2(p2.x, p2.y, ah[mt][2], al[mt][2]);
            split2(p3.x, p3.y, ah[mt][3], al[mt][3]);
        }
#pragma unroll
        for (int nt = 0; nt < 8; nt++) {
            int n = wn * 64 + nt * 8 + g;
            float2 q0 = *reinterpret_cast<const float2*>(&sVc[n * KBST + 2 * tig]);
            float2 q1 = *reinterpret_cast<const float2*>(&sVc[n * KBST + 2 * tig + 8]);
            uint32_t bh[2], bl[2];
            split2(q0.x, q0.y, bh[0], bl[0]);
            split2(q1.x, q1.y, bh[1], bl[1]);
#pragma unroll
            for (int mt = 0; mt < 2; mt++) {
                MMA_BF16(c[mt][nt], ah[mt], bh);
                MMA_BF16(c[mt][nt], ah[mt], bl);
                MMA_BF16(c[mt][nt], al[mt], bh);
            }
        }
        __syncthreads();
    }

    float* wvp = wv + ((size_t)s * LA_ + a0) * DV_;
#pragma unroll
    for (int mt = 0; mt < 2; mt++) {
        int r = wm * 32 + mt * 16 + g;
#pragma unroll
        for (int nt = 0; nt < 8; nt++) {
            int col = wn * 64 + nt * 8 + tig * 2;
            wvp[(size_t)r * DV_ + col]           = c[mt][nt][0];
            wvp[(size_t)r * DV_ + col + 1]       = c[mt][nt][1];
            wvp[(size_t)(r + 8) * DV_ + col]     = c[mt][nt][2];
            wvp[(size_t)(r + 8) * DV_ + col + 1] = c[mt][nt][3];
        }
    }
}

// ---------------------------------------------------------------------------
// Launch
// ---------------------------------------------------------------------------
extern "C" void kernel_launch(void* const* d_in, const int* in_sizes, int n_in,
                              void* d_out, int out_size) {
    const float* A      = (const float*)d_in[0];
    const float* B      = (const float*)d_in[1];
    const int*   a_lens = (const int*)  d_in[2];
    const int*   b_lens = (const int*)  d_in[3];
    const float* Wq     = (const float*)d_in[4];
    const float* bq     = (const float*)d_in[5];
    const float* gq     = (const float*)d_in[6];
    const float* betaq  = (const float*)d_in[7];
    const float* Wk     = (const float*)d_in[8];
    const float* bk     = (const float*)d_in[9];
    const float* gk     = (const float*)d_in[10];
    const float* betak  = (const float*)d_in[11];
    const float* Wv     = (const float*)d_in[12];
    const float* bv     = (const float*)d_in[13];
    const float* gv     = (const float*)d_in[14];
    const float* betav  = (const float*)d_in[15];
    const float* Wf     = (const float*)d_in[16];
    const float* bf     = (const float*)d_in[17];
    const float* gf     = (const float*)d_in[18];
    const float* betaf  = (const float*)d_in[19];
    float* out = (float*)d_out;

    float *Yq, *Yk, *Yv, *Ywv, *Yf, *Bp, *Wkp, *Wvp, *stats, *cnt;
    cudaGetSymbolAddress((void**)&Yq,   g_Yq);
    cudaGetSymbolAddress((void**)&Yk,   g_Yk);
    cudaGetSymbolAddress((void**)&Yv,   g_Yv);
    cudaGetSymbolAddress((void**)&Ywv,  g_Ywv);
    cudaGetSymbolAddress((void**)&Yf,   g_Yf);
    cudaGetSymbolAddress((void**)&Bp,   g_Bp);
    cudaGetSymbolAddress((void**)&Wkp,  g_Wkp);
    cudaGetSymbolAddress((void**)&Wvp,  g_Wvp);
    cudaGetSymbolAddress((void**)&stats, g_stats);
    cudaGetSymbolAddress((void**)&cnt,  g_cnt);

    cudaFuncSetAttribute(attention_tc,
                         cudaFuncAttributeMaxDynamicSharedMemorySize, ATT_SMEM_BYTES);

    float* sum_q = stats + 0 * 512;
    float* sq_q  = stats + 1 * 512;
    float* sum_k = stats + 2 * 512;
    float* sq_k  = stats + 3 * 512;
    float* sum_v = stats + 4 * 512;
    float* sq_v  = stats + 5 * 512;
    float* sum_f = stats + 6 * 512;
    float* sq_f  = stats + 7 * 512;

    // 0) fused init + fused pad                          (launch idx 0, 1)
    init_kernel<<<1, 256>>>(a_lens, b_lens);
    pad_all_kernel<<<ROWS_B + 1024, 128>>>(B, Wk, Wv, b_lens);

    // 1) projection GEMMs                                (launch idx 2, 3, 4)
    gemm_tc<<<dim3(DQK_ / 128, ROWS_A / 128), 256>>>(A,  Wq,  bq, Yq,
        ROWS_A, DQK_, DQ_, a_lens, 7, sum_q, sq_q);
    gemm_tc<<<dim3(DQK_ / 128, ROWS_B / 128), 256>>>(Bp, Wkp, bk, Yk,
        ROWS_B, DQK_, KPAD, b_lens, 9, sum_k, sq_k);
    gemm_tc<<<dim3(DV_ / 128, ROWS_B / 128), 256>>>(Bp, Wvp, bv, Yv,
        ROWS_B, DV_, KPAD, b_lens, 9, sum_v, sq_v);

    // 2) BN + ReLU + L2-normalize (in-place)
    bn_apply_kernel<<<ROWS_A / 2, 256>>>(Yq, DQK_, sum_q, sq_q, cnt + 0, gq, betaq,
                                         a_lens, LA_, 1, 0, nullptr);
    bn_apply_kernel<<<ROWS_B / 2, 256>>>(Yk, DQK_, sum_k, sq_k, cnt + 1, gk, betak,
                                         b_lens, LB_, 1, 0, nullptr);
    bn_apply_kernel<<<ROWS_B / 2, 256>>>(Yv, DV_,  sum_v, sq_v, cnt + 1, gv, betav,
                                         b_lens, LB_, 1, 0, nullptr);

    // 3) attention (valid-length bounded)
    attention_tc<<<dim3(S_, LA_ / 64), 512, ATT_SMEM_BYTES>>>(
        Yq, Yk, Yv, b_lens, a_lens, Ywv);

    // 4) final projection + BN + ReLU + output mask
    gemm_tc<<<dim3(DQ_ / 128, ROWS_A / 128), 256>>>(Ywv, Wf, bf, Yf,
        ROWS_A, DQ_, DV_, a_lens, 7, sum_f, sq_f);
    bn_apply_kernel<<<ROWS_A / 2, 256>>>(Yf, DQ_, sum_f, sq_f, cnt + 0, gf, betaf,
                                         a_lens, LA_, 0, 1, out);
}